// round 4
// baseline (speedup 1.0000x reference)
#include <cuda_runtime.h>
#include <cuda_bf16.h>
#include <cstdint>
#include <cstddef>

#define DEV_INLINE __device__ __forceinline__
typedef __nv_bfloat16 bf16;

constexpr int kB = 4, kC = 128, kH = 128, kW = 128;
constexpr int kHW = kH * kW;

// ======================= scratch (floats) =======================
constexpr size_t O_XT   = 0;
constexpr size_t O_H2F  = 8388608;
constexpr size_t O_OFFB = 16777216;
constexpr size_t O_XHI  = 20971520;
constexpr size_t O_XLO  = 25165824;
constexpr size_t O_H1HI = 29360128;
constexpr size_t O_H1LO = 33554432;
constexpr size_t O_H2HI = 37748736;
constexpr size_t O_H2LO = 41943040;
constexpr size_t O_H3HI = 46137344;
constexpr size_t O_H3LO = 50331648;
constexpr size_t O_W1HI = 54525952;
constexpr size_t O_W1LO = 54599680;
constexpr size_t O_W2HI = 54673408;
constexpr size_t O_W2LO = 54747136;
constexpr size_t O_WDHI = 54820864;
constexpr size_t O_WDLO = 54894592;
constexpr size_t O_WOHI = 54968320;
constexpr size_t O_WOLO = 55005184;
constexpr size_t O_WCHI = 55042048;
constexpr size_t O_WCLO = 55050240;
constexpr size_t O_SC   = 55058432;
constexpr size_t SCRATCH= 55060608;

__device__ float g_buf[SCRATCH];

// ======================= PTX helpers =======================
DEV_INLINE uint32_t smem_to_u32(const void* p) {
    uint32_t a;
    asm("{ .reg .u64 t; cvta.to.shared.u64 t, %1; cvt.u32.u64 %0, t; }" : "=r"(a) : "l"(p));
    return a;
}
DEV_INLINE void cp16(uint32_t d, const void* s, bool ok) {
    asm volatile("cp.async.ca.shared.global [%0], [%1], 16, %2;"
                 :: "r"(d), "l"(s), "r"(ok ? 16 : 0));
}
DEV_INLINE void cp_commit() { asm volatile("cp.async.commit_group;" ::: "memory"); }
DEV_INLINE void cp_wait0()  { asm volatile("cp.async.wait_group 0;" ::: "memory"); }
DEV_INLINE void cp_wait1()  { asm volatile("cp.async.wait_group 1;" ::: "memory"); }

DEV_INLINE void ldsm4(uint32_t a, uint32_t& r0, uint32_t& r1, uint32_t& r2, uint32_t& r3) {
    asm volatile("ldmatrix.sync.aligned.m8n8.x4.shared.b16 {%0,%1,%2,%3}, [%4];"
                 : "=r"(r0), "=r"(r1), "=r"(r2), "=r"(r3) : "r"(a));
}
DEV_INLINE void mma16816(float* c, const uint32_t* a, const uint32_t* b) {
    asm volatile("mma.sync.aligned.m16n8k16.row.col.f32.bf16.bf16.f32 "
                 "{%0,%1,%2,%3},{%4,%5,%6,%7},{%8,%9},{%0,%1,%2,%3};"
                 : "+f"(c[0]), "+f"(c[1]), "+f"(c[2]), "+f"(c[3])
                 : "r"(a[0]), "r"(a[1]), "r"(a[2]), "r"(a[3]), "r"(b[0]), "r"(b[1]));
}
DEV_INLINE void split_bf16(float v, bf16& h, bf16& l) {
    h = __float2bfloat16(v);
    l = __float2bfloat16(v - __bfloat162float(h));
}

// mma over one staged K-chunk: MT m-tiles x 8 n-tiles, KS k16 steps, 3 precision passes.
template <int MT, int KS>
DEV_INLINE void mma_chunk(uint32_t Ah, uint32_t Al, uint32_t Bh, uint32_t Bl,
                          int as, int bs, int pxb, int ocb, int lane, float (*acc)[4]) {
    const int r = lane & 7, sel = lane >> 3;
    const int aro = (pxb + (sel & 1) * 8 + r) * as;
    const int bro = (ocb + (sel >> 1) * 8 + r) * bs;
#pragma unroll
    for (int ks = 0; ks < KS; ks++) {
        const int ac = (ks * 16 + (sel >> 1) * 8) * 2;
        const int bc = (ks * 16 + (sel & 1) * 8) * 2;
        uint32_t ah[MT][4], al[MT][4];
#pragma unroll
        for (int mt = 0; mt < MT; mt++) {
            ldsm4(Ah + aro + mt * 16 * as + ac, ah[mt][0], ah[mt][1], ah[mt][2], ah[mt][3]);
            ldsm4(Al + aro + mt * 16 * as + ac, al[mt][0], al[mt][1], al[mt][2], al[mt][3]);
        }
        uint32_t bh[8][2], bl[8][2];
#pragma unroll
        for (int jp = 0; jp < 4; jp++) {
            ldsm4(Bh + bro + jp * 16 * bs + bc,
                  bh[2 * jp][0], bh[2 * jp][1], bh[2 * jp + 1][0], bh[2 * jp + 1][1]);
            ldsm4(Bl + bro + jp * 16 * bs + bc,
                  bl[2 * jp][0], bl[2 * jp][1], bl[2 * jp + 1][0], bl[2 * jp + 1][1]);
        }
#pragma unroll
        for (int mt = 0; mt < MT; mt++)
#pragma unroll
            for (int nt = 0; nt < 8; nt++) {
                float* c = acc[mt * 8 + nt];
                mma16816(c, ah[mt], bh[nt]);
                mma16816(c, ah[mt], bl[nt]);
                mma16816(c, al[mt], bh[nt]);
            }
    }
}

// ======================= prep kernels =======================
// fused BN preps: blockIdx selects which param set
__global__ void prep_bn_all_k(const float* __restrict__ rb_bn1, const float* __restrict__ rb_b1,
                              const float* __restrict__ rb_bn2, const float* __restrict__ rb_b2,
                              const float* __restrict__ bn1, const float* __restrict__ dc_b,
                              const float* __restrict__ bn2, const float* __restrict__ off_b,
                              float* __restrict__ scbase) {
    int which = blockIdx.x, c = threadIdx.x;
    if (which == 4) {
        if (c < 64) {
            scbase[8 * kC + c] = 1.f;                       // soff
            scbase[8 * kC + 64 + c] = (c < 54) ? off_b[c] : 0.f;  // toff
        }
        return;
    }
    const float* bnp = (which == 0) ? rb_bn1 : (which == 1) ? rb_bn2 : (which == 2) ? bn1 : bn2;
    const float* bias = (which == 0) ? rb_b1 : (which == 1) ? rb_b2 : (which == 2) ? dc_b : nullptr;
    float g = bnp[c], be = bnp[kC + c], m = bnp[2 * kC + c], va = bnp[3 * kC + c];
    float s = g / sqrtf(va + 1e-5f);
    float t = be - m * s;
    if (bias) t += bias[c] * s;
    scbase[which * 2 * kC + c] = s;
    scbase[which * 2 * kC + kC + c] = t;
}

// w [OC][128][3][3] -> [tap][OCP][128] bf16 hi/lo
__global__ void wprep3_k(const float* __restrict__ w, bf16* __restrict__ hi,
                         bf16* __restrict__ lo, int OC, int OCP) {
    int idx = blockIdx.x * 256 + threadIdx.x;
    if (idx >= 9 * OCP * kC) return;
    int ci = idx & 127, oc = (idx >> 7) % OCP, tap = idx / (OCP * kC);
    float v = (oc < OC) ? w[(oc * kC + ci) * 9 + tap] : 0.f;
    bf16 h, l; split_bf16(v, h, l);
    hi[idx] = h; lo[idx] = l;
}

// fused: offset weights + deform weights + 1x1 weights
__global__ void wprep_rest_k(const float* __restrict__ off_w, const float* __restrict__ dc_w,
                             const float* __restrict__ cv_w,
                             bf16* __restrict__ wohi, bf16* __restrict__ wolo,
                             bf16* __restrict__ wdhi, bf16* __restrict__ wdlo,
                             bf16* __restrict__ wchi, bf16* __restrict__ wclo) {
    int idx = blockIdx.x * 256 + threadIdx.x;
    if (idx < 73728) {
        // [tap][64oc][128ci], pad oc>=54
        int ci = idx & 127, oc = (idx >> 7) & 63, tap = idx >> 13;
        float v = (oc < 54) ? off_w[(oc * kC + ci) * 9 + tap] : 0.f;
        bf16 h, l; split_bf16(v, h, l);
        wohi[idx] = h; wolo[idx] = l;
    } else if (idx < 73728 + 147456) {
        int i2 = idx - 73728;  // [(d*9+k)][oc][cg64]
        int cg = i2 & 63, oc = (i2 >> 6) & 127, dk = i2 >> 13;
        int d = dk / 9, k = dk % 9;
        float v = dc_w[(oc * kC + d * 64 + cg) * 9 + k];
        bf16 h, l; split_bf16(v, h, l);
        wdhi[i2] = h; wdlo[i2] = l;
    } else if (idx < 73728 + 147456 + 16384) {
        int i3 = idx - 73728 - 147456;  // [oc][128]
        float v = cv_w[i3];
        bf16 h, l; split_bf16(v, h, l);
        wchi[i3] = h; wclo[i3] = l;
    }
}

// NCHW -> NHWC fp32 + bf16 hi/lo
__global__ void to_nhwc3_k(const float* __restrict__ in, float* __restrict__ outf,
                           bf16* __restrict__ ohi, bf16* __restrict__ olo) {
    __shared__ float t[32][33];
    int b = blockIdx.z, c0 = blockIdx.y * 32, p0 = blockIdx.x * 32;
    int tx = threadIdx.x, ty = threadIdx.y;
#pragma unroll
    for (int k = 0; k < 32; k += 8)
        t[ty + k][tx] = in[(size_t)(b * kC + c0 + ty + k) * kHW + p0 + tx];
    __syncthreads();
#pragma unroll
    for (int k = 0; k < 32; k += 8) {
        float v = t[tx][ty + k];
        size_t o = (size_t)(b * kHW + p0 + ty + k) * kC + c0 + tx;
        outf[o] = v;
        bf16 h, l; split_bf16(v, h, l);
        ohi[o] = h; olo[o] = l;
    }
}

// ======================= conv kernel (implicit GEMM, HMMA) =======================
// CTA: one image row (128 px) x NT oc. K chunks of 32 (tap x ci quarter).
// Single __syncthreads per chunk:
//   wait(stage c) -> barrier -> issue stage c+1 -> mma(c)
template <int NT, int EPI, int TAPS>
__global__ void __launch_bounds__(256)
mma_conv_k(const bf16* __restrict__ Ahi, const bf16* __restrict__ Alo,
           const bf16* __restrict__ Whi, const bf16* __restrict__ Wlo,
           const float* __restrict__ scale, const float* __restrict__ shift,
           const float* __restrict__ resf, float* __restrict__ outf,
           bf16* __restrict__ outhi, bf16* __restrict__ outlo) {
    constexpr int MT = NT / 64;
    constexpr int ASZ = 128 * 80;
    constexpr int BSZ = NT * 80;
    constexpr int NC = TAPS * 4;

    extern __shared__ char sm[];
    const uint32_t smA = smem_to_u32(sm);
    const uint32_t smB = smA + 4 * ASZ;

    const int h = blockIdx.x, b = blockIdx.y;
    const int tid = threadIdx.x, wid = tid >> 5, lane = tid & 31;
    const int wm = (NT == 128) ? (wid & 3) : wid;
    const int wn = (NT == 128) ? (wid >> 2) : 0;
    const int pxb = wm * MT * 16;
    const int ocb = wn * 64;

    float acc[MT * 8][4];
#pragma unroll
    for (int i = 0; i < MT * 8; i++)
#pragma unroll
        for (int j = 0; j < 4; j++) acc[i][j] = 0.f;

    auto stage = [&](int c, int s) {
        const int tap = c >> 2, c0 = (c & 3) * 32;
        const int ty = (TAPS == 9) ? tap / 3 - 1 : 0;
        const int tx = (TAPS == 9) ? tap % 3 - 1 : 0;
        const int row = h + ty;
        const bool rok = (row >= 0) && (row < kH);
#pragma unroll
        for (int it = 0; it < 4; it++) {
            int i = it * 256 + tid;
            int prec = i >> 9, rem = i & 511, px = rem >> 2, j = rem & 3;
            int col = px + tx;
            bool ok = rok && col >= 0 && col < kW;
            const bf16* src = (prec ? Alo : Ahi) +
                ((size_t)(b * kHW + (ok ? row * kW + col : 0)) * kC + c0 + j * 8);
            cp16(smA + (s * 2 + prec) * ASZ + px * 80 + j * 16, src, ok);
        }
#pragma unroll
        for (int it = 0; it < NT / 32; it++) {
            int i = it * 256 + tid;
            int prec = i / (NT * 4), rem = i % (NT * 4), oc = rem >> 2, j = rem & 3;
            const bf16* src = (prec ? Wlo : Whi) +
                ((size_t)(tap * NT + oc)) * kC + c0 + j * 8;
            cp16(smB + (s * 2 + prec) * BSZ + oc * 80 + j * 16, src, true);
        }
    };

    stage(0, 0); cp_commit();
#pragma unroll 1
    for (int c = 0; c < NC; c++) {
        const int s = c & 1;
        cp_wait0();
        __syncthreads();
        if (c + 1 < NC) { stage(c + 1, s ^ 1); cp_commit(); }
        mma_chunk<MT, 2>(smA + (s * 2 + 0) * ASZ, smA + (s * 2 + 1) * ASZ,
                         smB + (s * 2 + 0) * BSZ, smB + (s * 2 + 1) * BSZ,
                         80, 80, pxb, ocb, lane, acc);
    }

    // ---- epilogue ----
    const int r4 = lane >> 2, cp2 = (lane & 3) * 2;
    const size_t rowbase = (size_t)(b * kHW + h * kW);
#pragma unroll
    for (int mt = 0; mt < MT; mt++)
#pragma unroll
        for (int nt = 0; nt < 8; nt++) {
            const int oc = ocb + nt * 8 + cp2;
            const float s0 = scale[oc], s1 = scale[oc + 1];
            const float sh0 = shift[oc], sh1 = shift[oc + 1];
#pragma unroll
            for (int hh = 0; hh < 2; hh++) {
                const int px = pxb + mt * 16 + r4 + hh * 8;
                float v0 = acc[mt * 8 + nt][hh * 2 + 0] * s0 + sh0;
                float v1 = acc[mt * 8 + nt][hh * 2 + 1] * s1 + sh1;
                const size_t pix = rowbase + px;
                if (EPI == 1) {
                    float2 rr = *(const float2*)(resf + pix * kC + oc);
                    v0 += rr.x; v1 += rr.y;
                }
                if (EPI == 0 || EPI == 1) { v0 = fmaxf(v0, 0.f); v1 = fmaxf(v1, 0.f); }
                if (EPI == 4) {
                    v0 = (v0 > 0.f) ? v0 : 0.1f * v0;
                    v1 = (v1 > 0.f) ? v1 : 0.1f * v1;
                    size_t i0 = (size_t)(b * kC + oc) * kHW + h * kW + px;
                    outf[i0] = resf[i0] + v0;
                    outf[i0 + kHW] = resf[i0 + kHW] + v1;
                } else if (EPI == 2) {
                    *(float2*)(outf + pix * 64 + oc) = make_float2(v0, v1);
                } else {
                    bf16 h0, l0, h1, l1;
                    split_bf16(v0, h0, l0); split_bf16(v1, h1, l1);
                    *(__nv_bfloat162*)(outhi + pix * kC + oc) = __nv_bfloat162(h0, h1);
                    *(__nv_bfloat162*)(outlo + pix * kC + oc) = __nv_bfloat162(l0, l1);
                    if (EPI == 1)
                        *(float2*)(outf + pix * kC + oc) = make_float2(v0, v1);
                }
            }
        }
}

// ======================= modulated deformable conv =======================
// Gather hoisted into registers (overlaps previous mma); only STS + B-wait
// sit between the two barriers.
__global__ void __launch_bounds__(256)
mma_deform_k(const float* __restrict__ h2f, const float* __restrict__ offb,
             const bf16* __restrict__ Whi, const bf16* __restrict__ Wlo,
             const float* __restrict__ scale, const float* __restrict__ shift,
             bf16* __restrict__ outhi, bf16* __restrict__ outlo) {
    constexpr int ASZ = 128 * 144;   // per prec (single-buffered)
    constexpr int BSZ = 128 * 144;   // per prec per buf

    extern __shared__ char sm[];
    const uint32_t smA = smem_to_u32(sm);
    const uint32_t smB = smA + 2 * ASZ;

    const int h = blockIdx.x, b = blockIdx.y;
    const int tid = threadIdx.x, wid = tid >> 5, lane = tid & 31;
    const int wm = wid & 3, wn = wid >> 2;
    const int pxb = wm * 32, ocb = wn * 64;
    const int spx = tid >> 1, half = tid & 1;

    float acc[16][4];
#pragma unroll
    for (int i = 0; i < 16; i++)
#pragma unroll
        for (int j = 0; j < 4; j++) acc[i][j] = 0.f;

    auto stageB = [&](int dk, int s) {
#pragma unroll
        for (int it = 0; it < 8; it++) {
            int i = it * 256 + tid;
            int prec = i >> 10, rem = i & 1023, oc = rem >> 3, j = rem & 7;
            const bf16* src = (prec ? Wlo : Whi) + ((size_t)(dk * 128 + oc)) * 64 + j * 8;
            cp16(smB + (s * 2 + prec) * BSZ + oc * 144 + j * 16, src, true);
        }
    };

    const float* op = offb + ((size_t)(b * kHW + h * kW + spx)) * 64;

    stageB(0, 0); cp_commit();
#pragma unroll 1
    for (int dk = 0; dk < 18; dk++) {
        const int s = dk & 1;
        const int d = dk / 9, k = dk % 9;

        // ---- gather into registers (no smem traffic; overlaps others' mma) ----
        float oy = op[d * 18 + 2 * k], ox = op[d * 18 + 2 * k + 1];
        float ml = op[36 + d * 9 + k];
        float m = 1.f / (1.f + __expf(-ml));
        float py = oy + (float)(h + k / 3 - 1);
        float pxx = ox + (float)(spx + k % 3 - 1);
        float y0f = floorf(py), x0f = floorf(pxx);
        float fy = py - y0f, fx = pxx - x0f;
        int y0 = (int)y0f, x0 = (int)x0f;
        float cw[4] = {(1.f - fy) * (1.f - fx) * m, (1.f - fy) * fx * m,
                       fy * (1.f - fx) * m, fy * fx * m};
        int cy[4] = {y0, y0, y0 + 1, y0 + 1};
        int cx[4] = {x0, x0 + 1, x0, x0 + 1};
        float rr[32];
#pragma unroll
        for (int j = 0; j < 32; j++) rr[j] = 0.f;
        const float* bp = h2f + (size_t)b * kHW * kC + d * 64 + half * 32;
#pragma unroll
        for (int cn = 0; cn < 4; cn++) {
            int y = cy[cn], x = cx[cn];
            if (y >= 0 && y < kH && x >= 0 && x < kW) {
                const float4* p4 = (const float4*)(bp + (size_t)(y * kW + x) * kC);
                float wg = cw[cn];
#pragma unroll
                for (int q = 0; q < 8; q++) {
                    float4 u4 = p4[q];
                    rr[q * 4 + 0] += wg * u4.x; rr[q * 4 + 1] += wg * u4.y;
                    rr[q * 4 + 2] += wg * u4.z; rr[q * 4 + 3] += wg * u4.w;
                }
            }
        }
        __align__(16) bf16 hb[32], lb[32];
#pragma unroll
        for (int j = 0; j < 32; j++) split_bf16(rr[j], hb[j], lb[j]);

        __syncthreads();   // all warps finished mma(dk-1): A + B[s] safe to overwrite
        {
            uint32_t base = spx * 144 + half * 64;
#pragma unroll
            for (int q = 0; q < 4; q++) {
                *(uint4*)(sm + (0 * ASZ) + base + q * 16) = ((uint4*)hb)[q];
                *(uint4*)(sm + (1 * ASZ) + base + q * 16) = ((uint4*)lb)[q];
            }
        }
        if (dk + 1 < 18) { stageB(dk + 1, s ^ 1); cp_commit(); cp_wait1(); }
        else cp_wait0();
        __syncthreads();   // STS + B(dk) visible

        mma_chunk<2, 4>(smA, smA + ASZ,
                        smB + (s * 2 + 0) * BSZ, smB + (s * 2 + 1) * BSZ,
                        144, 144, pxb, ocb, lane, acc);
    }

    // ---- epilogue: leaky(bn) -> hi/lo NHWC ----
    const int r4 = lane >> 2, cp2 = (lane & 3) * 2;
    const size_t rowbase = (size_t)(b * kHW + h * kW);
#pragma unroll
    for (int mt = 0; mt < 2; mt++)
#pragma unroll
        for (int nt = 0; nt < 8; nt++) {
            const int oc = ocb + nt * 8 + cp2;
            const float s0 = scale[oc], s1 = scale[oc + 1];
            const float sh0 = shift[oc], sh1 = shift[oc + 1];
#pragma unroll
            for (int hh = 0; hh < 2; hh++) {
                const int px = pxb + mt * 16 + r4 + hh * 8;
                float v0 = acc[mt * 8 + nt][hh * 2 + 0] * s0 + sh0;
                float v1 = acc[mt * 8 + nt][hh * 2 + 1] * s1 + sh1;
                v0 = (v0 > 0.f) ? v0 : 0.1f * v0;
                v1 = (v1 > 0.f) ? v1 : 0.1f * v1;
                const size_t pix = rowbase + px;
                bf16 h0, l0, h1, l1;
                split_bf16(v0, h0, l0); split_bf16(v1, h1, l1);
                *(__nv_bfloat162*)(outhi + pix * kC + oc) = __nv_bfloat162(h0, h1);
                *(__nv_bfloat162*)(outlo + pix * kC + oc) = __nv_bfloat162(l0, l1);
            }
        }
}

// ======================= launch =======================
extern "C" void kernel_launch(void* const* d_in, const int* in_sizes, int n_in,
                              void* d_out, int out_size) {
    (void)in_sizes; (void)n_in; (void)out_size;
    const float* x      = (const float*)d_in[0];
    const float* rb_w1  = (const float*)d_in[1];
    const float* rb_b1  = (const float*)d_in[2];
    const float* rb_bn1 = (const float*)d_in[3];
    const float* rb_w2  = (const float*)d_in[4];
    const float* rb_b2  = (const float*)d_in[5];
    const float* rb_bn2 = (const float*)d_in[6];
    const float* off_w  = (const float*)d_in[7];
    const float* off_b  = (const float*)d_in[8];
    const float* dc_w   = (const float*)d_in[9];
    const float* dc_b   = (const float*)d_in[10];
    const float* bn1    = (const float*)d_in[11];
    const float* cv2_w  = (const float*)d_in[12];
    const float* bn2    = (const float*)d_in[13];
    float* out = (float*)d_out;

    float* base = nullptr;
    cudaGetSymbolAddress((void**)&base, g_buf);
    float* xt    = base + O_XT;
    float* h2f   = base + O_H2F;
    float* offb_ = base + O_OFFB;
    bf16* xhi  = (bf16*)(base + O_XHI);
    bf16* xlo  = (bf16*)(base + O_XLO);
    bf16* h1hi = (bf16*)(base + O_H1HI);
    bf16* h1lo = (bf16*)(base + O_H1LO);
    bf16* h2hi = (bf16*)(base + O_H2HI);
    bf16* h2lo = (bf16*)(base + O_H2LO);
    bf16* h3hi = (bf16*)(base + O_H3HI);
    bf16* h3lo = (bf16*)(base + O_H3LO);
    bf16* w1hi = (bf16*)(base + O_W1HI);
    bf16* w1lo = (bf16*)(base + O_W1LO);
    bf16* w2hi = (bf16*)(base + O_W2HI);
    bf16* w2lo = (bf16*)(base + O_W2LO);
    bf16* wdhi = (bf16*)(base + O_WDHI);
    bf16* wdlo = (bf16*)(base + O_WDLO);
    bf16* wohi = (bf16*)(base + O_WOHI);
    bf16* wolo = (bf16*)(base + O_WOLO);
    bf16* wchi = (bf16*)(base + O_WCHI);
    bf16* wclo = (bf16*)(base + O_WCLO);
    float* scb = base + O_SC;
    float* s1 = scb + 0 * kC;   float* t1 = scb + 1 * kC;
    float* s2 = scb + 2 * kC;   float* t2 = scb + 3 * kC;
    float* s3 = scb + 4 * kC;   float* t3 = scb + 5 * kC;
    float* s4 = scb + 6 * kC;   float* t4 = scb + 7 * kC;
    float* soff = scb + 8 * kC; float* toff = soff + 64;

    // prep — exactly 5 launches before conv1 so ncu (-s 5) profiles conv1
    wprep3_k<<<(9 * kC * kC + 255) / 256, 256>>>(rb_w1, w1hi, w1lo, kC, kC);      // 0
    wprep3_k<<<(9 * kC * kC + 255) / 256, 256>>>(rb_w2, w2hi, w2lo, kC, kC);      // 1
    wprep_rest_k<<<(73728 + 147456 + 16384 + 255) / 256, 256>>>(                   // 2
        off_w, dc_w, cv2_w, wohi, wolo, wdhi, wdlo, wchi, wclo);
    prep_bn_all_k<<<5, kC>>>(rb_bn1, rb_b1, rb_bn2, rb_b2, bn1, dc_b, bn2, off_b, scb);  // 3
    to_nhwc3_k<<<dim3(kHW / 32, kC / 32, kB), dim3(32, 8)>>>(x, xt, xhi, xlo);     // 4

    constexpr int SM128 = 4 * (128 * 80) + 4 * (128 * 80);
    constexpr int SM64  = 4 * (128 * 80) + 4 * (64 * 80);
    constexpr int SMDEF = 2 * (128 * 144) + 4 * (128 * 144);
    dim3 grid(kH, kB);

    cudaFuncSetAttribute(mma_conv_k<128, 0, 9>, cudaFuncAttributeMaxDynamicSharedMemorySize, SM128);
    cudaFuncSetAttribute(mma_conv_k<128, 1, 9>, cudaFuncAttributeMaxDynamicSharedMemorySize, SM128);
    cudaFuncSetAttribute(mma_conv_k<64, 2, 9>,  cudaFuncAttributeMaxDynamicSharedMemorySize, SM64);
    cudaFuncSetAttribute(mma_conv_k<128, 4, 1>, cudaFuncAttributeMaxDynamicSharedMemorySize, SM128);
    cudaFuncSetAttribute(mma_deform_k,          cudaFuncAttributeMaxDynamicSharedMemorySize, SMDEF);

    mma_conv_k<128, 0, 9><<<grid, 256, SM128>>>(xhi, xlo, w1hi, w1lo, s1, t1,      // 5  <- ncu
                                                nullptr, nullptr, h1hi, h1lo);
    mma_conv_k<128, 1, 9><<<grid, 256, SM128>>>(h1hi, h1lo, w2hi, w2lo, s2, t2,
                                                xt, h2f, h2hi, h2lo);
    mma_conv_k<64, 2, 9><<<grid, 256, SM64>>>(h2hi, h2lo, wohi, wolo, soff, toff,
                                              nullptr, offb_, nullptr, nullptr);
    mma_deform_k<<<grid, 256, SMDEF>>>(h2f, offb_, wdhi, wdlo, s3, t3, h3hi, h3lo);
    mma_conv_k<128, 4, 1><<<grid, 256, SM128>>>(h3hi, h3lo, wchi, wclo, s4, t4,
                                                x, out, nullptr, nullptr);
}

// round 7
// speedup vs baseline: 1.3438x; 1.3438x over previous
#include <cuda_runtime.h>
#include <cuda_fp16.h>
#include <cstdint>
#include <cstddef>

#define DEV_INLINE __device__ __forceinline__

constexpr int kB = 4, kC = 128, kH = 128, kW = 128;
constexpr int kHW = kH * kW;

// ======================= scratch (floats) =======================
constexpr size_t O_XT   = 0;
constexpr size_t O_H2F  = 8388608;
constexpr size_t O_OFFB = 16777216;
constexpr size_t O_XHI  = 20971520;   // fp16 arrays (each 8.4M halves = 4194304 floats)
constexpr size_t O_XLO  = 25165824;
constexpr size_t O_H1HI = 29360128;
constexpr size_t O_H1LO = 33554432;
constexpr size_t O_H2HI = 37748736;
constexpr size_t O_H2LO = 41943040;
constexpr size_t O_H3HI = 46137344;
constexpr size_t O_H3LO = 50331648;
constexpr size_t O_W1   = 54525952;   // single fp16 weights now
constexpr size_t O_W2   = 54599680;
constexpr size_t O_WD   = 54673408;
constexpr size_t O_WO   = 54747136;
constexpr size_t O_WC   = 54820864;
constexpr size_t O_SC   = 55058432;
constexpr size_t SCRATCH= 55060608;

__device__ float g_buf[SCRATCH];

// ======================= PTX helpers =======================
DEV_INLINE uint32_t smem_to_u32(const void* p) {
    uint32_t a;
    asm("{ .reg .u64 t; cvta.to.shared.u64 t, %1; cvt.u32.u64 %0, t; }" : "=r"(a) : "l"(p));
    return a;
}
DEV_INLINE void cp16(uint32_t d, const void* s, bool ok) {
    asm volatile("cp.async.ca.shared.global [%0], [%1], 16, %2;"
                 :: "r"(d), "l"(s), "r"(ok ? 16 : 0));
}
DEV_INLINE void cp_commit() { asm volatile("cp.async.commit_group;" ::: "memory"); }
DEV_INLINE void cp_wait0()  { asm volatile("cp.async.wait_group 0;" ::: "memory"); }
DEV_INLINE void cp_wait1()  { asm volatile("cp.async.wait_group 1;" ::: "memory"); }

DEV_INLINE void ldsm4(uint32_t a, uint32_t& r0, uint32_t& r1, uint32_t& r2, uint32_t& r3) {
    asm volatile("ldmatrix.sync.aligned.m8n8.x4.shared.b16 {%0,%1,%2,%3}, [%4];"
                 : "=r"(r0), "=r"(r1), "=r"(r2), "=r"(r3) : "r"(a));
}
DEV_INLINE void mma16816(float* c, const uint32_t* a, const uint32_t* b) {
    asm volatile("mma.sync.aligned.m16n8k16.row.col.f32.f16.f16.f32 "
                 "{%0,%1,%2,%3},{%4,%5,%6,%7},{%8,%9},{%0,%1,%2,%3};"
                 : "+f"(c[0]), "+f"(c[1]), "+f"(c[2]), "+f"(c[3])
                 : "r"(a[0]), "r"(a[1]), "r"(a[2]), "r"(a[3]), "r"(b[0]), "r"(b[1]));
}
DEV_INLINE void split_half(float v, __half& h, __half& l) {
    h = __float2half_rn(v);
    l = __float2half_rn(v - __half2float(h));
}

// mma over one staged K-chunk: MT m-tiles x 8 n-tiles, KS k16 steps, 2 passes (Ah,Al) x B.
template <int MT, int KS>
DEV_INLINE void mma_chunk(uint32_t Ah, uint32_t Al, uint32_t B,
                          int as, int bs, int pxb, int ocb, int lane, float (*acc)[4]) {
    const int r = lane & 7, sel = lane >> 3;
    const int aro = (pxb + (sel & 1) * 8 + r) * as;
    const int bro = (ocb + (sel >> 1) * 8 + r) * bs;
#pragma unroll
    for (int ks = 0; ks < KS; ks++) {
        const int ac = (ks * 16 + (sel >> 1) * 8) * 2;
        const int bc = (ks * 16 + (sel & 1) * 8) * 2;
        uint32_t ah[MT][4], al[MT][4];
#pragma unroll
        for (int mt = 0; mt < MT; mt++) {
            ldsm4(Ah + aro + mt * 16 * as + ac, ah[mt][0], ah[mt][1], ah[mt][2], ah[mt][3]);
            ldsm4(Al + aro + mt * 16 * as + ac, al[mt][0], al[mt][1], al[mt][2], al[mt][3]);
        }
        uint32_t bh[8][2];
#pragma unroll
        for (int jp = 0; jp < 4; jp++) {
            ldsm4(B + bro + jp * 16 * bs + bc,
                  bh[2 * jp][0], bh[2 * jp][1], bh[2 * jp + 1][0], bh[2 * jp + 1][1]);
        }
#pragma unroll
        for (int mt = 0; mt < MT; mt++)
#pragma unroll
            for (int nt = 0; nt < 8; nt++) {
                float* c = acc[mt * 8 + nt];
                mma16816(c, ah[mt], bh[nt]);
                mma16816(c, al[mt], bh[nt]);
            }
    }
}

// ======================= prep kernels =======================
__global__ void prep_bn_all_k(const float* __restrict__ rb_bn1, const float* __restrict__ rb_b1,
                              const float* __restrict__ rb_bn2, const float* __restrict__ rb_b2,
                              const float* __restrict__ bn1, const float* __restrict__ dc_b,
                              const float* __restrict__ bn2, const float* __restrict__ off_b,
                              float* __restrict__ scbase) {
    int which = blockIdx.x, c = threadIdx.x;
    if (which == 4) {
        if (c < 64) {
            scbase[8 * kC + c] = 1.f;
            scbase[8 * kC + 64 + c] = (c < 54) ? off_b[c] : 0.f;
        }
        return;
    }
    const float* bnp = (which == 0) ? rb_bn1 : (which == 1) ? rb_bn2 : (which == 2) ? bn1 : bn2;
    const float* bias = (which == 0) ? rb_b1 : (which == 1) ? rb_b2 : (which == 2) ? dc_b : nullptr;
    float g = bnp[c], be = bnp[kC + c], m = bnp[2 * kC + c], va = bnp[3 * kC + c];
    float s = g / sqrtf(va + 1e-5f);
    float t = be - m * s;
    if (bias) t += bias[c] * s;
    scbase[which * 2 * kC + c] = s;
    scbase[which * 2 * kC + kC + c] = t;
}

// single mega weight-prep: all five weight tensors -> fp16
__global__ void wprep_all_k(const float* __restrict__ rb_w1, const float* __restrict__ rb_w2,
                            const float* __restrict__ off_w, const float* __restrict__ dc_w,
                            const float* __restrict__ cv_w,
                            __half* __restrict__ w1, __half* __restrict__ w2,
                            __half* __restrict__ wo, __half* __restrict__ wd,
                            __half* __restrict__ wc) {
    int idx = blockIdx.x * 256 + threadIdx.x;
    if (idx < 147456) {
        // rb_w1: [tap][128oc][128ci]
        int ci = idx & 127, oc = (idx >> 7) & 127, tap = idx >> 14;
        w1[idx] = __float2half_rn(rb_w1[(oc * kC + ci) * 9 + tap]);
    } else if (idx < 294912) {
        int i = idx - 147456;
        int ci = i & 127, oc = (i >> 7) & 127, tap = i >> 14;
        w2[i] = __float2half_rn(rb_w2[(oc * kC + ci) * 9 + tap]);
    } else if (idx < 368640) {
        int i = idx - 294912;   // [tap][64oc][128ci], pad oc>=54
        int ci = i & 127, oc = (i >> 7) & 63, tap = i >> 13;
        wo[i] = __float2half_rn((oc < 54) ? off_w[(oc * kC + ci) * 9 + tap] : 0.f);
    } else if (idx < 516096) {
        int i = idx - 368640;   // [(d*9+k)][128oc][64cg]
        int cg = i & 63, oc = (i >> 6) & 127, dk = i >> 13;
        int d = dk / 9, k = dk % 9;
        wd[i] = __float2half_rn(dc_w[(oc * kC + d * 64 + cg) * 9 + k]);
    } else if (idx < 532480) {
        int i = idx - 516096;   // [oc][128ci]
        wc[i] = __float2half_rn(cv_w[i]);
    }
}

// NCHW -> NHWC fp32 + fp16 hi/lo
__global__ void to_nhwc3_k(const float* __restrict__ in, float* __restrict__ outf,
                           __half* __restrict__ ohi, __half* __restrict__ olo) {
    __shared__ float t[32][33];
    int b = blockIdx.z, c0 = blockIdx.y * 32, p0 = blockIdx.x * 32;
    int tx = threadIdx.x, ty = threadIdx.y;
#pragma unroll
    for (int k = 0; k < 32; k += 8)
        t[ty + k][tx] = in[(size_t)(b * kC + c0 + ty + k) * kHW + p0 + tx];
    __syncthreads();
#pragma unroll
    for (int k = 0; k < 32; k += 8) {
        float v = t[tx][ty + k];
        size_t o = (size_t)(b * kHW + p0 + ty + k) * kC + c0 + tx;
        outf[o] = v;
        __half h, l; split_half(v, h, l);
        ohi[o] = h; olo[o] = l;
    }
}

// ======================= conv kernel (implicit GEMM, fp16 HMMA, 2-pass) =======================
// CTA: one image row (128 px) x NT oc. K chunks of 32 (tap x ci quarter).
template <int NT, int EPI, int TAPS>
__global__ void __launch_bounds__(256)
mma_conv_k(const __half* __restrict__ Ahi, const __half* __restrict__ Alo,
           const __half* __restrict__ W,
           const float* __restrict__ scale, const float* __restrict__ shift,
           const float* __restrict__ resf, float* __restrict__ outf,
           __half* __restrict__ outhi, __half* __restrict__ outlo) {
    constexpr int MT = NT / 64;
    constexpr int ASZ = 128 * 80;   // per prec per buf
    constexpr int BSZ = NT * 80;    // single prec per buf
    constexpr int NC = TAPS * 4;

    extern __shared__ char sm[];
    const uint32_t smA = smem_to_u32(sm);
    const uint32_t smB = smA + 4 * ASZ;

    const int h = blockIdx.x, b = blockIdx.y;
    const int tid = threadIdx.x, wid = tid >> 5, lane = tid & 31;
    const int wm = (NT == 128) ? (wid & 3) : wid;
    const int wn = (NT == 128) ? (wid >> 2) : 0;
    const int pxb = wm * MT * 16;
    const int ocb = wn * 64;

    float acc[MT * 8][4];
#pragma unroll
    for (int i = 0; i < MT * 8; i++)
#pragma unroll
        for (int j = 0; j < 4; j++) acc[i][j] = 0.f;

    auto stage = [&](int c, int s) {
        const int tap = c >> 2, c0 = (c & 3) * 32;
        const int ty = (TAPS == 9) ? tap / 3 - 1 : 0;
        const int tx = (TAPS == 9) ? tap % 3 - 1 : 0;
        const int row = h + ty;
        const bool rok = (row >= 0) && (row < kH);
        // A: 128 px x 32 ci x 2 prec
#pragma unroll
        for (int it = 0; it < 4; it++) {
            int i = it * 256 + tid;
            int prec = i >> 9, rem = i & 511, px = rem >> 2, j = rem & 3;
            int col = px + tx;
            bool ok = rok && col >= 0 && col < kW;
            const __half* src = (prec ? Alo : Ahi) +
                ((size_t)(b * kHW + (ok ? row * kW + col : 0)) * kC + c0 + j * 8);
            cp16(smA + (s * 2 + prec) * ASZ + px * 80 + j * 16, src, ok);
        }
        // B: NT oc x 32 ci, single prec
#pragma unroll
        for (int it = 0; it < NT / 64; it++) {
            int i = it * 256 + tid;
            int oc = i >> 2, j = i & 3;
            const __half* src = W + ((size_t)(tap * NT + oc)) * kC + c0 + j * 8;
            cp16(smB + s * BSZ + oc * 80 + j * 16, src, true);
        }
    };

    stage(0, 0); cp_commit();
#pragma unroll 1
    for (int c = 0; c < NC; c++) {
        const int s = c & 1;
        cp_wait0();
        __syncthreads();
        if (c + 1 < NC) { stage(c + 1, s ^ 1); cp_commit(); }
        mma_chunk<MT, 2>(smA + (s * 2 + 0) * ASZ, smA + (s * 2 + 1) * ASZ,
                         smB + s * BSZ, 80, 80, pxb, ocb, lane, acc);
    }

    // ---- epilogue ----
    const int r4 = lane >> 2, cp2 = (lane & 3) * 2;
    const size_t rowbase = (size_t)(b * kHW + h * kW);
#pragma unroll
    for (int mt = 0; mt < MT; mt++)
#pragma unroll
        for (int nt = 0; nt < 8; nt++) {
            const int oc = ocb + nt * 8 + cp2;
            const float s0 = scale[oc], s1 = scale[oc + 1];
            const float sh0 = shift[oc], sh1 = shift[oc + 1];
#pragma unroll
            for (int hh = 0; hh < 2; hh++) {
                const int px = pxb + mt * 16 + r4 + hh * 8;
                float v0 = acc[mt * 8 + nt][hh * 2 + 0] * s0 + sh0;
                float v1 = acc[mt * 8 + nt][hh * 2 + 1] * s1 + sh1;
                const size_t pix = rowbase + px;
                if (EPI == 1) {
                    float2 rr = *(const float2*)(resf + pix * kC + oc);
                    v0 += rr.x; v1 += rr.y;
                }
                if (EPI == 0 || EPI == 1) { v0 = fmaxf(v0, 0.f); v1 = fmaxf(v1, 0.f); }
                if (EPI == 4) {
                    v0 = (v0 > 0.f) ? v0 : 0.1f * v0;
                    v1 = (v1 > 0.f) ? v1 : 0.1f * v1;
                    size_t i0 = (size_t)(b * kC + oc) * kHW + h * kW + px;
                    outf[i0] = resf[i0] + v0;
                    outf[i0 + kHW] = resf[i0 + kHW] + v1;
                } else if (EPI == 2) {
                    *(float2*)(outf + pix * 64 + oc) = make_float2(v0, v1);
                } else {
                    __half h0, l0, h1, l1;
                    split_half(v0, h0, l0); split_half(v1, h1, l1);
                    *(__half2*)(outhi + pix * kC + oc) = __halves2half2(h0, h1);
                    *(__half2*)(outlo + pix * kC + oc) = __halves2half2(l0, l1);
                    if (EPI == 1)
                        *(float2*)(outf + pix * kC + oc) = make_float2(v0, v1);
                }
            }
        }
}

// ======================= modulated deformable conv =======================
__global__ void __launch_bounds__(256)
mma_deform_k(const float* __restrict__ h2f, const float* __restrict__ offb,
             const __half* __restrict__ W,
             const float* __restrict__ scale, const float* __restrict__ shift,
             __half* __restrict__ outhi, __half* __restrict__ outlo) {
    constexpr int ASZ = 128 * 144;   // per prec (single-buffered)
    constexpr int BSZ = 128 * 144;   // single prec per buf

    extern __shared__ char sm[];
    const uint32_t smA = smem_to_u32(sm);
    const uint32_t smB = smA + 2 * ASZ;

    const int h = blockIdx.x, b = blockIdx.y;
    const int tid = threadIdx.x, wid = tid >> 5, lane = tid & 31;
    const int wm = wid & 3, wn = wid >> 2;
    const int pxb = wm * 32, ocb = wn * 64;
    const int spx = tid >> 1, half = tid & 1;

    float acc[16][4];
#pragma unroll
    for (int i = 0; i < 16; i++)
#pragma unroll
        for (int j = 0; j < 4; j++) acc[i][j] = 0.f;

    auto stageB = [&](int dk, int s) {
        // 128 oc x 64 cg fp16: 1024 cp16s
#pragma unroll
        for (int it = 0; it < 4; it++) {
            int i = it * 256 + tid;
            int oc = i >> 3, j = i & 7;
            const __half* src = W + ((size_t)(dk * 128 + oc)) * 64 + j * 8;
            cp16(smB + s * BSZ + oc * 144 + j * 16, src, true);
        }
    };

    const float* op = offb + ((size_t)(b * kHW + h * kW + spx)) * 64;

    stageB(0, 0); cp_commit();
#pragma unroll 1
    for (int dk = 0; dk < 18; dk++) {
        const int s = dk & 1;
        const int d = dk / 9, k = dk % 9;

        // ---- gather into registers (overlaps other warps' mma) ----
        float oy = op[d * 18 + 2 * k], ox = op[d * 18 + 2 * k + 1];
        float ml = op[36 + d * 9 + k];
        float m = 1.f / (1.f + __expf(-ml));
        float py = oy + (float)(h + k / 3 - 1);
        float pxx = ox + (float)(spx + k % 3 - 1);
        float y0f = floorf(py), x0f = floorf(pxx);
        float fy = py - y0f, fx = pxx - x0f;
        int y0 = (int)y0f, x0 = (int)x0f;
        float cw[4] = {(1.f - fy) * (1.f - fx) * m, (1.f - fy) * fx * m,
                       fy * (1.f - fx) * m, fy * fx * m};
        int cy[4] = {y0, y0, y0 + 1, y0 + 1};
        int cx[4] = {x0, x0 + 1, x0, x0 + 1};
        float rr[32];
#pragma unroll
        for (int j = 0; j < 32; j++) rr[j] = 0.f;
        const float* bp = h2f + (size_t)b * kHW * kC + d * 64 + half * 32;
#pragma unroll
        for (int cn = 0; cn < 4; cn++) {
            int y = cy[cn], x = cx[cn];
            if (y >= 0 && y < kH && x >= 0 && x < kW) {
                const float4* p4 = (const float4*)(bp + (size_t)(y * kW + x) * kC);
                float wg = cw[cn];
#pragma unroll
                for (int q = 0; q < 8; q++) {
                    float4 u4 = p4[q];
                    rr[q * 4 + 0] += wg * u4.x; rr[q * 4 + 1] += wg * u4.y;
                    rr[q * 4 + 2] += wg * u4.z; rr[q * 4 + 3] += wg * u4.w;
                }
            }
        }
        __align__(16) __half hb[32], lb[32];
#pragma unroll
        for (int j = 0; j < 32; j++) split_half(rr[j], hb[j], lb[j]);

        __syncthreads();   // mma(dk-1) done: A + B[s] safe to overwrite
        {
            uint32_t base = spx * 144 + half * 64;
#pragma unroll
            for (int q = 0; q < 4; q++) {
                *(uint4*)(sm + 0 * ASZ + base + q * 16) = ((uint4*)hb)[q];
                *(uint4*)(sm + 1 * ASZ + base + q * 16) = ((uint4*)lb)[q];
            }
        }
        if (dk + 1 < 18) { stageB(dk + 1, s ^ 1); cp_commit(); cp_wait1(); }
        else cp_wait0();
        __syncthreads();

        mma_chunk<2, 4>(smA, smA + ASZ, smB + s * BSZ,
                        144, 144, pxb, ocb, lane, acc);
    }

    // ---- epilogue: leaky(bn) -> hi/lo NHWC ----
    const int r4 = lane >> 2, cp2 = (lane & 3) * 2;
    const size_t rowbase = (size_t)(b * kHW + h * kW);
#pragma unroll
    for (int mt = 0; mt < 2; mt++)
#pragma unroll
        for (int nt = 0; nt < 8; nt++) {
            const int oc = ocb + nt * 8 + cp2;
            const float s0 = scale[oc], s1 = scale[oc + 1];
            const float sh0 = shift[oc], sh1 = shift[oc + 1];
#pragma unroll
            for (int hh = 0; hh < 2; hh++) {
                const int px = pxb + mt * 16 + r4 + hh * 8;
                float v0 = acc[mt * 8 + nt][hh * 2 + 0] * s0 + sh0;
                float v1 = acc[mt * 8 + nt][hh * 2 + 1] * s1 + sh1;
                v0 = (v0 > 0.f) ? v0 : 0.1f * v0;
                v1 = (v1 > 0.f) ? v1 : 0.1f * v1;
                const size_t pix = rowbase + px;
                __half h0, l0, h1, l1;
                split_half(v0, h0, l0); split_half(v1, h1, l1);
                *(__half2*)(outhi + pix * kC + oc) = __halves2half2(h0, h1);
                *(__half2*)(outlo + pix * kC + oc) = __halves2half2(l0, l1);
            }
        }
}

// ======================= launch =======================
extern "C" void kernel_launch(void* const* d_in, const int* in_sizes, int n_in,
                              void* d_out, int out_size) {
    (void)in_sizes; (void)n_in; (void)out_size;
    const float* x      = (const float*)d_in[0];
    const float* rb_w1  = (const float*)d_in[1];
    const float* rb_b1  = (const float*)d_in[2];
    const float* rb_bn1 = (const float*)d_in[3];
    const float* rb_w2  = (const float*)d_in[4];
    const float* rb_b2  = (const float*)d_in[5];
    const float* rb_bn2 = (const float*)d_in[6];
    const float* off_w  = (const float*)d_in[7];
    const float* off_b  = (const float*)d_in[8];
    const float* dc_w   = (const float*)d_in[9];
    const float* dc_b   = (const float*)d_in[10];
    const float* bn1    = (const float*)d_in[11];
    const float* cv2_w  = (const float*)d_in[12];
    const float* bn2    = (const float*)d_in[13];
    float* out = (float*)d_out;

    float* base = nullptr;
    cudaGetSymbolAddress((void**)&base, g_buf);
    float* xt    = base + O_XT;
    float* h2f   = base + O_H2F;
    float* offb_ = base + O_OFFB;
    __half* xhi  = (__half*)(base + O_XHI);
    __half* xlo  = (__half*)(base + O_XLO);
    __half* h1hi = (__half*)(base + O_H1HI);
    __half* h1lo = (__half*)(base + O_H1LO);
    __half* h2hi = (__half*)(base + O_H2HI);
    __half* h2lo = (__half*)(base + O_H2LO);
    __half* h3hi = (__half*)(base + O_H3HI);
    __half* h3lo = (__half*)(base + O_H3LO);
    __half* w1 = (__half*)(base + O_W1);
    __half* w2 = (__half*)(base + O_W2);
    __half* wd = (__half*)(base + O_WD);
    __half* wo = (__half*)(base + O_WO);
    __half* wc = (__half*)(base + O_WC);
    float* scb = base + O_SC;
    float* s1 = scb + 0 * kC;   float* t1 = scb + 1 * kC;
    float* s2 = scb + 2 * kC;   float* t2 = scb + 3 * kC;
    float* s3 = scb + 4 * kC;   float* t3 = scb + 5 * kC;
    float* s4 = scb + 6 * kC;   float* t4 = scb + 7 * kC;
    float* soff = scb + 8 * kC; float* toff = soff + 64;

    // prep — 3 launches, so conv1 sits at launch index 3 (what ncu captures)
    wprep_all_k<<<(532480 + 255) / 256, 256>>>(rb_w1, rb_w2, off_w, dc_w, cv2_w,   // 0
                                               w1, w2, wo, wd, wc);
    prep_bn_all_k<<<5, kC>>>(rb_bn1, rb_b1, rb_bn2, rb_b2, bn1, dc_b, bn2, off_b, scb);  // 1
    to_nhwc3_k<<<dim3(kHW / 32, kC / 32, kB), dim3(32, 8)>>>(x, xt, xhi, xlo);     // 2

    constexpr int SM128 = 4 * (128 * 80) + 2 * (128 * 80);   // 61440
    constexpr int SM64  = 4 * (128 * 80) + 2 * (64 * 80);    // 51200
    constexpr int SMDEF = 2 * (128 * 144) + 2 * (128 * 144); // 73728
    dim3 grid(kH, kB);

    cudaFuncSetAttribute(mma_conv_k<128, 0, 9>, cudaFuncAttributeMaxDynamicSharedMemorySize, SM128);
    cudaFuncSetAttribute(mma_conv_k<128, 1, 9>, cudaFuncAttributeMaxDynamicSharedMemorySize, SM128);
    cudaFuncSetAttribute(mma_conv_k<64, 2, 9>,  cudaFuncAttributeMaxDynamicSharedMemorySize, SM64);
    cudaFuncSetAttribute(mma_conv_k<128, 4, 1>, cudaFuncAttributeMaxDynamicSharedMemorySize, SM128);
    cudaFuncSetAttribute(mma_deform_k,          cudaFuncAttributeMaxDynamicSharedMemorySize, SMDEF);

    mma_conv_k<128, 0, 9><<<grid, 256, SM128>>>(xhi, xlo, w1, s1, t1,              // 3 <- ncu
                                                nullptr, nullptr, h1hi, h1lo);
    mma_conv_k<128, 1, 9><<<grid, 256, SM128>>>(h1hi, h1lo, w2, s2, t2,
                                                xt, h2f, h2hi, h2lo);
    mma_conv_k<64, 2, 9><<<grid, 256, SM64>>>(h2hi, h2lo, wo, soff, toff,
                                              nullptr, offb_, nullptr, nullptr);
    mma_deform_k<<<grid, 256, SMDEF>>>(h2f, offb_, wd, s3, t3, h3hi, h3lo);
    mma_conv_k<128, 4, 1><<<grid, 256, SM128>>>(h3hi, h3lo, wc, s4, t4,
                                                x, out, nullptr, nullptr);
}

// round 11
// speedup vs baseline: 1.3583x; 1.0109x over previous
#include <cuda_runtime.h>
#include <cuda_fp16.h>
#include <cstdint>
#include <cstddef>

#define DEV_INLINE __device__ __forceinline__

constexpr int kB = 4, kC = 128, kH = 128, kW = 128;
constexpr int kHW = kH * kW;

// ======================= scratch (floats) =======================
constexpr size_t O_XT   = 0;
constexpr size_t O_H2F  = 8388608;
constexpr size_t O_OFFB = 16777216;
constexpr size_t O_XHI  = 20971520;
constexpr size_t O_XLO  = 25165824;
constexpr size_t O_H1HI = 29360128;
constexpr size_t O_H1LO = 33554432;
constexpr size_t O_H2HI = 37748736;
constexpr size_t O_H2LO = 41943040;
constexpr size_t O_H3HI = 46137344;
constexpr size_t O_H3LO = 50331648;
constexpr size_t O_W1   = 54525952;
constexpr size_t O_W2   = 54599680;
constexpr size_t O_WD   = 54673408;
constexpr size_t O_WO   = 54747136;
constexpr size_t O_WC   = 54820864;
constexpr size_t O_SC   = 55058432;
constexpr size_t SCRATCH= 55060608;

__device__ float g_buf[SCRATCH];

// ======================= PTX helpers =======================
DEV_INLINE uint32_t smem_to_u32(const void* p) {
    uint32_t a;
    asm("{ .reg .u64 t; cvta.to.shared.u64 t, %1; cvt.u32.u64 %0, t; }" : "=r"(a) : "l"(p));
    return a;
}
DEV_INLINE void cp16(uint32_t d, const void* s, bool ok) {
    asm volatile("cp.async.ca.shared.global [%0], [%1], 16, %2;"
                 :: "r"(d), "l"(s), "r"(ok ? 16 : 0));
}
DEV_INLINE void cp_commit() { asm volatile("cp.async.commit_group;" ::: "memory"); }
DEV_INLINE void cp_wait0()  { asm volatile("cp.async.wait_group 0;" ::: "memory"); }
DEV_INLINE void cp_wait1()  { asm volatile("cp.async.wait_group 1;" ::: "memory"); }

DEV_INLINE void ldsm4(uint32_t a, uint32_t& r0, uint32_t& r1, uint32_t& r2, uint32_t& r3) {
    asm volatile("ldmatrix.sync.aligned.m8n8.x4.shared.b16 {%0,%1,%2,%3}, [%4];"
                 : "=r"(r0), "=r"(r1), "=r"(r2), "=r"(r3) : "r"(a));
}
DEV_INLINE void mma16816(float* c, const uint32_t* a, const uint32_t* b) {
    asm volatile("mma.sync.aligned.m16n8k16.row.col.f32.f16.f16.f32 "
                 "{%0,%1,%2,%3},{%4,%5,%6,%7},{%8,%9},{%0,%1,%2,%3};"
                 : "+f"(c[0]), "+f"(c[1]), "+f"(c[2]), "+f"(c[3])
                 : "r"(a[0]), "r"(a[1]), "r"(a[2]), "r"(a[3]), "r"(b[0]), "r"(b[1]));
}
DEV_INLINE void split_half(float v, __half& h, __half& l) {
    h = __float2half_rn(v);
    l = __float2half_rn(v - __half2float(h));
}

// mma over one staged K-chunk: MT m-tiles x 8 n-tiles, KS k16 steps, 2 passes (Ah,Al) x B.
template <int MT, int KS>
DEV_INLINE void mma_chunk(uint32_t Ah, uint32_t Al, uint32_t B,
                          int as, int bs, int pxb, int ocb, int lane, float (*acc)[4]) {
    const int r = lane & 7, sel = lane >> 3;
    const int aro = (pxb + (sel & 1) * 8 + r) * as;
    const int bro = (ocb + (sel >> 1) * 8 + r) * bs;
#pragma unroll
    for (int ks = 0; ks < KS; ks++) {
        const int ac = (ks * 16 + (sel >> 1) * 8) * 2;
        const int bc = (ks * 16 + (sel & 1) * 8) * 2;
        uint32_t ah[MT][4], al[MT][4];
#pragma unroll
        for (int mt = 0; mt < MT; mt++) {
            ldsm4(Ah + aro + mt * 16 * as + ac, ah[mt][0], ah[mt][1], ah[mt][2], ah[mt][3]);
            ldsm4(Al + aro + mt * 16 * as + ac, al[mt][0], al[mt][1], al[mt][2], al[mt][3]);
        }
        uint32_t bh[8][2];
#pragma unroll
        for (int jp = 0; jp < 4; jp++) {
            ldsm4(B + bro + jp * 16 * bs + bc,
                  bh[2 * jp][0], bh[2 * jp][1], bh[2 * jp + 1][0], bh[2 * jp + 1][1]);
        }
#pragma unroll
        for (int mt = 0; mt < MT; mt++)
#pragma unroll
            for (int nt = 0; nt < 8; nt++) {
                float* c = acc[mt * 8 + nt];
                mma16816(c, ah[mt], bh[nt]);
                mma16816(c, al[mt], bh[nt]);
            }
    }
}

// ======================= prep kernels =======================
__global__ void prep_bn_all_k(const float* __restrict__ rb_bn1, const float* __restrict__ rb_b1,
                              const float* __restrict__ rb_bn2, const float* __restrict__ rb_b2,
                              const float* __restrict__ bn1, const float* __restrict__ dc_b,
                              const float* __restrict__ bn2, const float* __restrict__ off_b,
                              float* __restrict__ scbase) {
    int which = blockIdx.x, c = threadIdx.x;
    if (which == 4) {
        if (c < 64) {
            scbase[8 * kC + c] = 1.f;
            scbase[8 * kC + 64 + c] = (c < 54) ? off_b[c] : 0.f;
        }
        return;
    }
    const float* bnp = (which == 0) ? rb_bn1 : (which == 1) ? rb_bn2 : (which == 2) ? bn1 : bn2;
    const float* bias = (which == 0) ? rb_b1 : (which == 1) ? rb_b2 : (which == 2) ? dc_b : nullptr;
    float g = bnp[c], be = bnp[kC + c], m = bnp[2 * kC + c], va = bnp[3 * kC + c];
    float s = g / sqrtf(va + 1e-5f);
    float t = be - m * s;
    if (bias) t += bias[c] * s;
    scbase[which * 2 * kC + c] = s;
    scbase[which * 2 * kC + kC + c] = t;
}

__global__ void wprep_all_k(const float* __restrict__ rb_w1, const float* __restrict__ rb_w2,
                            const float* __restrict__ off_w, const float* __restrict__ dc_w,
                            const float* __restrict__ cv_w,
                            __half* __restrict__ w1, __half* __restrict__ w2,
                            __half* __restrict__ wo, __half* __restrict__ wd,
                            __half* __restrict__ wc) {
    int idx = blockIdx.x * 256 + threadIdx.x;
    if (idx < 147456) {
        int ci = idx & 127, oc = (idx >> 7) & 127, tap = idx >> 14;
        w1[idx] = __float2half_rn(rb_w1[(oc * kC + ci) * 9 + tap]);
    } else if (idx < 294912) {
        int i = idx - 147456;
        int ci = i & 127, oc = (i >> 7) & 127, tap = i >> 14;
        w2[i] = __float2half_rn(rb_w2[(oc * kC + ci) * 9 + tap]);
    } else if (idx < 368640) {
        int i = idx - 294912;
        int ci = i & 127, oc = (i >> 7) & 63, tap = i >> 13;
        wo[i] = __float2half_rn((oc < 54) ? off_w[(oc * kC + ci) * 9 + tap] : 0.f);
    } else if (idx < 516096) {
        int i = idx - 368640;
        int cg = i & 63, oc = (i >> 6) & 127, dk = i >> 13;
        int d = dk / 9, k = dk % 9;
        wd[i] = __float2half_rn(dc_w[(oc * kC + d * 64 + cg) * 9 + k]);
    } else if (idx < 532480) {
        int i = idx - 516096;
        wc[i] = __float2half_rn(cv_w[i]);
    }
}

__global__ void to_nhwc3_k(const float* __restrict__ in, float* __restrict__ outf,
                           __half* __restrict__ ohi, __half* __restrict__ olo) {
    __shared__ float t[32][33];
    int b = blockIdx.z, c0 = blockIdx.y * 32, p0 = blockIdx.x * 32;
    int tx = threadIdx.x, ty = threadIdx.y;
#pragma unroll
    for (int k = 0; k < 32; k += 8)
        t[ty + k][tx] = in[(size_t)(b * kC + c0 + ty + k) * kHW + p0 + tx];
    __syncthreads();
#pragma unroll
    for (int k = 0; k < 32; k += 8) {
        float v = t[tx][ty + k];
        size_t o = (size_t)(b * kHW + p0 + ty + k) * kC + c0 + tx;
        outf[o] = v;
        __half h, l; split_half(v, h, l);
        ohi[o] = h; olo[o] = l;
    }
}

// ======================= conv kernel (row-reuse implicit GEMM, fp16 2-pass) =======================
// CTA: one image row (128 px) x NT oc. Outer chunks: (ty in 0..NTY-1) x (ci quarter).
// One A-stage (haloed 130 px) serves 3 tx taps via ldmatrix base shifts (+80 B = +1 px).
template <int NT, int EPI, int TAPS>
__global__ void __launch_bounds__(256, 2)
mma_conv_k(const __half* __restrict__ Ahi, const __half* __restrict__ Alo,
           const __half* __restrict__ W,
           const float* __restrict__ scale, const float* __restrict__ shift,
           const float* __restrict__ resf, float* __restrict__ outf,
           __half* __restrict__ outhi, __half* __restrict__ outlo) {
    constexpr int MT   = NT / 64;
    constexpr int HALO = (TAPS == 9) ? 1 : 0;
    constexpr int NTX  = (TAPS == 9) ? 3 : 1;
    constexpr int NTY  = NTX;
    constexpr int PXS  = 128 + 2 * HALO;        // staged slots (in-px = slot - HALO)
    constexpr int PXSP = (TAPS == 9) ? 136 : 128;
    constexpr int APREC = PXSP * 80;            // bytes per precision
    constexpr int APB   = 2 * APREC;            // A bytes per buffer
    constexpr int BPT   = NT * 80;              // B bytes per tap
    constexpr int BPB   = NTX * BPT;            // B bytes per buffer
    constexpr int NCH   = NTY * 4;              // staging chunks

    extern __shared__ char sm[];
    const uint32_t smA = smem_to_u32(sm);
    const uint32_t smB = smA + 2 * APB;

    const int h = blockIdx.x, b = blockIdx.y;
    const int tid = threadIdx.x, wid = tid >> 5, lane = tid & 31;
    const int wm = (NT == 128) ? (wid & 3) : wid;
    const int wn = (NT == 128) ? (wid >> 2) : 0;
    const int pxb = wm * MT * 16;
    const int ocb = wn * 64;

    float acc[MT * 8][4];
#pragma unroll
    for (int i = 0; i < MT * 8; i++)
#pragma unroll
        for (int j = 0; j < 4; j++) acc[i][j] = 0.f;

    auto stage = [&](int cc, int s) {
        const int ty = cc >> 2, cq = cc & 3, c0 = cq * 32;
        const int row = h + ty - HALO;
        const bool rok = (row >= 0) && (row < kH);
        // A: PXS slots x 32 ci x 2 prec
        constexpr int ATOT = PXS * 8;   // cp16 count
#pragma unroll
        for (int it = 0; it < (ATOT + 255) / 256; it++) {
            int i = it * 256 + tid;
            if ((ATOT & 255) && i >= ATOT) break;
            int prec = i / (PXS * 4), rem = i % (PXS * 4), slot = rem >> 2, j = rem & 3;
            int inpx = slot - HALO;
            bool ok = rok && ((unsigned)inpx < 128u);
            const __half* src = (prec ? Alo : Ahi) +
                ((size_t)(b * kHW + (ok ? row * kW + inpx : 0)) * kC + c0 + j * 8);
            cp16(smA + s * APB + prec * APREC + slot * 80 + j * 16, src, ok);
        }
        // B: NTX taps x NT oc x 32 ci
#pragma unroll
        for (int it = 0; it < NTX * NT / 64; it++) {
            int i = it * 256 + tid;
            int txn = i / (NT * 4), rem = i % (NT * 4), oc = rem >> 2, j = rem & 3;
            int tap = ty * 3 + txn;
            const __half* src = W + ((size_t)(tap * NT + oc)) * kC + c0 + j * 8;
            cp16(smB + s * BPB + txn * BPT + oc * 80 + j * 16, src, true);
        }
    };

    stage(0, 0); cp_commit();
#pragma unroll 1
    for (int cc = 0; cc < NCH; cc++) {
        const int s = cc & 1;
        cp_wait0();
        __syncthreads();
        if (cc + 1 < NCH) { stage(cc + 1, s ^ 1); cp_commit(); }
#pragma unroll
        for (int tx = 0; tx < NTX; tx++) {
            // out-px p reads slot p + tx  (in-px = p + tx - HALO)
            mma_chunk<MT, 2>(smA + s * APB + tx * 80,
                             smA + s * APB + APREC + tx * 80,
                             smB + s * BPB + tx * BPT,
                             80, 80, pxb, ocb, lane, acc);
        }
    }

    // ---- epilogue ----
    const int r4 = lane >> 2, cp2 = (lane & 3) * 2;
    const size_t rowbase = (size_t)(b * kHW + h * kW);
#pragma unroll
    for (int mt = 0; mt < MT; mt++)
#pragma unroll
        for (int nt = 0; nt < 8; nt++) {
            const int oc = ocb + nt * 8 + cp2;
            const float s0 = scale[oc], s1 = scale[oc + 1];
            const float sh0 = shift[oc], sh1 = shift[oc + 1];
#pragma unroll
            for (int hh = 0; hh < 2; hh++) {
                const int px = pxb + mt * 16 + r4 + hh * 8;
                float v0 = acc[mt * 8 + nt][hh * 2 + 0] * s0 + sh0;
                float v1 = acc[mt * 8 + nt][hh * 2 + 1] * s1 + sh1;
                const size_t pix = rowbase + px;
                if (EPI == 1) {
                    float2 rr = *(const float2*)(resf + pix * kC + oc);
                    v0 += rr.x; v1 += rr.y;
                }
                if (EPI == 0 || EPI == 1) { v0 = fmaxf(v0, 0.f); v1 = fmaxf(v1, 0.f); }
                if (EPI == 4) {
                    v0 = (v0 > 0.f) ? v0 : 0.1f * v0;
                    v1 = (v1 > 0.f) ? v1 : 0.1f * v1;
                    size_t i0 = (size_t)(b * kC + oc) * kHW + h * kW + px;
                    outf[i0] = resf[i0] + v0;
                    outf[i0 + kHW] = resf[i0 + kHW] + v1;
                } else if (EPI == 2) {
                    *(float2*)(outf + pix * 64 + oc) = make_float2(v0, v1);
                } else {
                    __half h0, l0, h1, l1;
                    split_half(v0, h0, l0); split_half(v1, h1, l1);
                    *(__half2*)(outhi + pix * kC + oc) = __halves2half2(h0, h1);
                    *(__half2*)(outlo + pix * kC + oc) = __halves2half2(l0, l1);
                    if (EPI == 1)
                        *(float2*)(outf + pix * kC + oc) = make_float2(v0, v1);
                }
            }
        }
}

// ======================= modulated deformable conv (single-barrier pipeline) =======================
__global__ void __launch_bounds__(256, 2)
mma_deform_k(const float* __restrict__ h2f, const float* __restrict__ offb,
             const __half* __restrict__ W,
             const float* __restrict__ scale, const float* __restrict__ shift,
             __half* __restrict__ outhi, __half* __restrict__ outlo) {
    constexpr int APREC = 128 * 144;   // 18432 per precision
    constexpr int ABUF  = 2 * APREC;   // per A buffer
    constexpr int BSZ   = 128 * 144;   // per B buffer

    extern __shared__ char sm[];
    const uint32_t smA = smem_to_u32(sm);
    const uint32_t smB = smA + 2 * ABUF;

    const int h = blockIdx.x, b = blockIdx.y;
    const int tid = threadIdx.x, wid = tid >> 5, lane = tid & 31;
    const int wm = wid & 3, wn = wid >> 2;
    const int pxb = wm * 32, ocb = wn * 64;
    const int spx = tid >> 1, half = tid & 1;

    float acc[16][4];
#pragma unroll
    for (int i = 0; i < 16; i++)
#pragma unroll
        for (int j = 0; j < 4; j++) acc[i][j] = 0.f;

    const float* op = offb + ((size_t)(b * kHW + h * kW + spx)) * 64;

    auto gath = [&](int dk, __half* hb, __half* lb) {
        int d = dk / 9, k = dk % 9;
        float oy = op[d * 18 + 2 * k], ox = op[d * 18 + 2 * k + 1];
        float ml = op[36 + d * 9 + k];
        float m = 1.f / (1.f + __expf(-ml));
        float py = oy + (float)(h + k / 3 - 1);
        float pxx = ox + (float)(spx + k % 3 - 1);
        float y0f = floorf(py), x0f = floorf(pxx);
        float fy = py - y0f, fx = pxx - x0f;
        int y0 = (int)y0f, x0 = (int)x0f;
        float cw[4] = {(1.f - fy) * (1.f - fx) * m, (1.f - fy) * fx * m,
                       fy * (1.f - fx) * m, fy * fx * m};
        int cy[4] = {y0, y0, y0 + 1, y0 + 1};
        int cx[4] = {x0, x0 + 1, x0, x0 + 1};
        float rr[32];
#pragma unroll
        for (int j = 0; j < 32; j++) rr[j] = 0.f;
        const float* bp = h2f + (size_t)b * kHW * kC + d * 64 + half * 32;
#pragma unroll
        for (int cn = 0; cn < 4; cn++) {
            int y = cy[cn], x = cx[cn];
            if (y >= 0 && y < kH && x >= 0 && x < kW) {
                const float4* p4 = (const float4*)(bp + (size_t)(y * kW + x) * kC);
                float wg = cw[cn];
#pragma unroll
                for (int q = 0; q < 8; q++) {
                    float4 u4 = p4[q];
                    rr[q * 4 + 0] += wg * u4.x; rr[q * 4 + 1] += wg * u4.y;
                    rr[q * 4 + 2] += wg * u4.z; rr[q * 4 + 3] += wg * u4.w;
                }
            }
        }
#pragma unroll
        for (int j = 0; j < 32; j++) split_half(rr[j], hb[j], lb[j]);
    };

    auto sts = [&](int s, const __half* hb, const __half* lb) {
        uint32_t bofs = spx * 144 + half * 64;
#pragma unroll
        for (int q = 0; q < 4; q++) {
            *(uint4*)(sm + (size_t)s * ABUF + bofs + q * 16) = ((const uint4*)hb)[q];
            *(uint4*)(sm + (size_t)s * ABUF + APREC + bofs + q * 16) = ((const uint4*)lb)[q];
        }
    };

    auto stageB = [&](int dk, int s) {
#pragma unroll
        for (int it = 0; it < 4; it++) {
            int i = it * 256 + tid;
            int oc = i >> 3, j = i & 7;
            const __half* src = W + ((size_t)(dk * 128 + oc)) * 64 + j * 8;
            cp16(smB + s * BSZ + oc * 144 + j * 16, src, true);
        }
    };

    __align__(16) __half hb[32], lb[32];
    gath(0, hb, lb);
    sts(0, hb, lb);
    stageB(0, 0); cp_commit();

#pragma unroll 1
    for (int dk = 0; dk < 18; dk++) {
        const int s = dk & 1;
        const bool more = (dk + 1 < 18);
        if (more) {
            gath(dk + 1, hb, lb);            // overlaps other warps' mma(dk-1)
            stageB(dk + 1, s ^ 1); cp_commit();
            cp_wait1();                      // B(dk) landed
        } else {
            cp_wait0();
        }
        __syncthreads();                     // mma(dk-1) done everywhere; STS(dk) visible
        if (more) sts(s ^ 1, hb, lb);        // overlaps mma(dk) of other warps
        mma_chunk<2, 4>(smA + s * ABUF, smA + s * ABUF + APREC, smB + s * BSZ,
                        144, 144, pxb, ocb, lane, acc);
    }

    // ---- epilogue: leaky(bn) -> hi/lo NHWC ----
    const int r4 = lane >> 2, cp2 = (lane & 3) * 2;
    const size_t rowbase = (size_t)(b * kHW + h * kW);
#pragma unroll
    for (int mt = 0; mt < 2; mt++)
#pragma unroll
        for (int nt = 0; nt < 8; nt++) {
            const int oc = ocb + nt * 8 + cp2;
            const float s0 = scale[oc], s1 = scale[oc + 1];
            const float sh0 = shift[oc], sh1 = shift[oc + 1];
#pragma unroll
            for (int hh = 0; hh < 2; hh++) {
                const int px = pxb + mt * 16 + r4 + hh * 8;
                float v0 = acc[mt * 8 + nt][hh * 2 + 0] * s0 + sh0;
                float v1 = acc[mt * 8 + nt][hh * 2 + 1] * s1 + sh1;
                v0 = (v0 > 0.f) ? v0 : 0.1f * v0;
                v1 = (v1 > 0.f) ? v1 : 0.1f * v1;
                const size_t pix = rowbase + px;
                __half h0, l0, h1, l1;
                split_half(v0, h0, l0); split_half(v1, h1, l1);
                *(__half2*)(outhi + pix * kC + oc) = __halves2half2(h0, h1);
                *(__half2*)(outlo + pix * kC + oc) = __halves2half2(l0, l1);
            }
        }
}

// ======================= launch =======================
extern "C" void kernel_launch(void* const* d_in, const int* in_sizes, int n_in,
                              void* d_out, int out_size) {
    (void)in_sizes; (void)n_in; (void)out_size;
    const float* x      = (const float*)d_in[0];
    const float* rb_w1  = (const float*)d_in[1];
    const float* rb_b1  = (const float*)d_in[2];
    const float* rb_bn1 = (const float*)d_in[3];
    const float* rb_w2  = (const float*)d_in[4];
    const float* rb_b2  = (const float*)d_in[5];
    const float* rb_bn2 = (const float*)d_in[6];
    const float* off_w  = (const float*)d_in[7];
    const float* off_b  = (const float*)d_in[8];
    const float* dc_w   = (const float*)d_in[9];
    const float* dc_b   = (const float*)d_in[10];
    const float* bn1    = (const float*)d_in[11];
    const float* cv2_w  = (const float*)d_in[12];
    const float* bn2    = (const float*)d_in[13];
    float* out = (float*)d_out;

    float* base = nullptr;
    cudaGetSymbolAddress((void**)&base, g_buf);
    float* xt    = base + O_XT;
    float* h2f   = base + O_H2F;
    float* offb_ = base + O_OFFB;
    __half* xhi  = (__half*)(base + O_XHI);
    __half* xlo  = (__half*)(base + O_XLO);
    __half* h1hi = (__half*)(base + O_H1HI);
    __half* h1lo = (__half*)(base + O_H1LO);
    __half* h2hi = (__half*)(base + O_H2HI);
    __half* h2lo = (__half*)(base + O_H2LO);
    __half* h3hi = (__half*)(base + O_H3HI);
    __half* h3lo = (__half*)(base + O_H3LO);
    __half* w1 = (__half*)(base + O_W1);
    __half* w2 = (__half*)(base + O_W2);
    __half* wd = (__half*)(base + O_WD);
    __half* wo = (__half*)(base + O_WO);
    __half* wc = (__half*)(base + O_WC);
    float* scb = base + O_SC;
    float* s1 = scb + 0 * kC;   float* t1 = scb + 1 * kC;
    float* s2 = scb + 2 * kC;   float* t2 = scb + 3 * kC;
    float* s3 = scb + 4 * kC;   float* t3 = scb + 5 * kC;
    float* s4 = scb + 6 * kC;   float* t4 = scb + 7 * kC;
    float* soff = scb + 8 * kC; float* toff = soff + 64;

    wprep_all_k<<<(532480 + 255) / 256, 256>>>(rb_w1, rb_w2, off_w, dc_w, cv2_w,
                                               w1, w2, wo, wd, wc);
    prep_bn_all_k<<<5, kC>>>(rb_bn1, rb_b1, rb_bn2, rb_b2, bn1, dc_b, bn2, off_b, scb);
    to_nhwc3_k<<<dim3(kHW / 32, kC / 32, kB), dim3(32, 8)>>>(x, xt, xhi, xlo);

    // smem: 2*(2*PXSP*80) + 2*(NTX*NT*80)
    constexpr int SM1  = 2 * (2 * 136 * 80) + 2 * (3 * 128 * 80);  // 104960
    constexpr int SMO  = 2 * (2 * 136 * 80) + 2 * (3 * 64 * 80);   // 74240
    constexpr int SMC  = 2 * (2 * 128 * 80) + 2 * (1 * 128 * 80);  // 61440
    constexpr int SMDEF = 2 * (2 * 128 * 144) + 2 * (128 * 144);   // 110592
    dim3 grid(kH, kB);

    cudaFuncSetAttribute(mma_conv_k<128, 0, 9>, cudaFuncAttributeMaxDynamicSharedMemorySize, SM1);
    cudaFuncSetAttribute(mma_conv_k<128, 1, 9>, cudaFuncAttributeMaxDynamicSharedMemorySize, SM1);
    cudaFuncSetAttribute(mma_conv_k<64, 2, 9>,  cudaFuncAttributeMaxDynamicSharedMemorySize, SMO);
    cudaFuncSetAttribute(mma_conv_k<128, 4, 1>, cudaFuncAttributeMaxDynamicSharedMemorySize, SMC);
    cudaFuncSetAttribute(mma_deform_k,          cudaFuncAttributeMaxDynamicSharedMemorySize, SMDEF);

    mma_conv_k<128, 0, 9><<<grid, 256, SM1>>>(xhi, xlo, w1, s1, t1,
                                              nullptr, nullptr, h1hi, h1lo);
    mma_conv_k<128, 1, 9><<<grid, 256, SM1>>>(h1hi, h1lo, w2, s2, t2,
                                              xt, h2f, h2hi, h2lo);
    mma_conv_k<64, 2, 9><<<grid, 256, SMO>>>(h2hi, h2lo, wo, soff, toff,
                                             nullptr, offb_, nullptr, nullptr);
    mma_deform_k<<<grid, 256, SMDEF>>>(h2f, offb_, wd, s3, t3, h3hi, h3lo);
    mma_conv_k<128, 4, 1><<<grid, 256, SMC>>>(h3hi, h3lo, wc, s4, t4,
                                              x, out, nullptr, nullptr);
}

// round 12
// speedup vs baseline: 1.7856x; 1.3145x over previous
#include <cuda_runtime.h>
#include <cuda_fp16.h>
#include <cstdint>
#include <cstddef>

#define DEV_INLINE __device__ __forceinline__

constexpr int kB = 4, kC = 128, kH = 128, kW = 128;
constexpr int kHW = kH * kW;

// ======================= scratch (floats) =======================
constexpr size_t O_XT   = 0;
constexpr size_t O_H2F  = 8388608;
constexpr size_t O_OFFB = 16777216;
constexpr size_t O_XH   = 20971520;   // fp16 activations (each 8.4M halves)
constexpr size_t O_H1H  = 25165824;
constexpr size_t O_H2H  = 29360128;
constexpr size_t O_H3H  = 33554432;
constexpr size_t O_W1   = 54525952;
constexpr size_t O_W2   = 54599680;
constexpr size_t O_WD   = 54673408;
constexpr size_t O_WO   = 54747136;
constexpr size_t O_WC   = 54820864;
constexpr size_t O_SC   = 55058432;
constexpr size_t SCRATCH= 55060608;

__device__ float g_buf[SCRATCH];

// ======================= PTX helpers =======================
DEV_INLINE uint32_t smem_to_u32(const void* p) {
    uint32_t a;
    asm("{ .reg .u64 t; cvta.to.shared.u64 t, %1; cvt.u32.u64 %0, t; }" : "=r"(a) : "l"(p));
    return a;
}
DEV_INLINE void cp16(uint32_t d, const void* s, bool ok) {
    asm volatile("cp.async.ca.shared.global [%0], [%1], 16, %2;"
                 :: "r"(d), "l"(s), "r"(ok ? 16 : 0));
}
DEV_INLINE void cp_commit() { asm volatile("cp.async.commit_group;" ::: "memory"); }
DEV_INLINE void cp_wait0()  { asm volatile("cp.async.wait_group 0;" ::: "memory"); }
DEV_INLINE void cp_wait1()  { asm volatile("cp.async.wait_group 1;" ::: "memory"); }

DEV_INLINE void ldsm4(uint32_t a, uint32_t& r0, uint32_t& r1, uint32_t& r2, uint32_t& r3) {
    asm volatile("ldmatrix.sync.aligned.m8n8.x4.shared.b16 {%0,%1,%2,%3}, [%4];"
                 : "=r"(r0), "=r"(r1), "=r"(r2), "=r"(r3) : "r"(a));
}
DEV_INLINE void mma16816(float* c, const uint32_t* a, const uint32_t* b) {
    asm volatile("mma.sync.aligned.m16n8k16.row.col.f32.f16.f16.f32 "
                 "{%0,%1,%2,%3},{%4,%5,%6,%7},{%8,%9},{%0,%1,%2,%3};"
                 : "+f"(c[0]), "+f"(c[1]), "+f"(c[2]), "+f"(c[3])
                 : "r"(a[0]), "r"(a[1]), "r"(a[2]), "r"(a[3]), "r"(b[0]), "r"(b[1]));
}

// single-pass mma over one staged K-chunk: MT m-tiles x 8 n-tiles, KS k16 steps.
template <int MT, int KS>
DEV_INLINE void mma_chunk(uint32_t A, uint32_t B,
                          int as, int bs, int pxb, int ocb, int lane, float (*acc)[4]) {
    const int r = lane & 7, sel = lane >> 3;
    const int aro = (pxb + (sel & 1) * 8 + r) * as;
    const int bro = (ocb + (sel >> 1) * 8 + r) * bs;
#pragma unroll
    for (int ks = 0; ks < KS; ks++) {
        const int ac = (ks * 16 + (sel >> 1) * 8) * 2;
        const int bc = (ks * 16 + (sel & 1) * 8) * 2;
        uint32_t ah[MT][4];
#pragma unroll
        for (int mt = 0; mt < MT; mt++)
            ldsm4(A + aro + mt * 16 * as + ac, ah[mt][0], ah[mt][1], ah[mt][2], ah[mt][3]);
        uint32_t bh[8][2];
#pragma unroll
        for (int jp = 0; jp < 4; jp++) {
            ldsm4(B + bro + jp * 16 * bs + bc,
                  bh[2 * jp][0], bh[2 * jp][1], bh[2 * jp + 1][0], bh[2 * jp + 1][1]);
        }
#pragma unroll
        for (int mt = 0; mt < MT; mt++)
#pragma unroll
            for (int nt = 0; nt < 8; nt++)
                mma16816(acc[mt * 8 + nt], ah[mt], bh[nt]);
    }
}

// ======================= prep kernels =======================
__global__ void prep_bn_all_k(const float* __restrict__ rb_bn1, const float* __restrict__ rb_b1,
                              const float* __restrict__ rb_bn2, const float* __restrict__ rb_b2,
                              const float* __restrict__ bn1, const float* __restrict__ dc_b,
                              const float* __restrict__ bn2, const float* __restrict__ off_b,
                              float* __restrict__ scbase) {
    int which = blockIdx.x, c = threadIdx.x;
    if (which == 4) {
        if (c < 64) {
            scbase[8 * kC + c] = 1.f;
            scbase[8 * kC + 64 + c] = (c < 54) ? off_b[c] : 0.f;
        }
        return;
    }
    const float* bnp = (which == 0) ? rb_bn1 : (which == 1) ? rb_bn2 : (which == 2) ? bn1 : bn2;
    const float* bias = (which == 0) ? rb_b1 : (which == 1) ? rb_b2 : (which == 2) ? dc_b : nullptr;
    float g = bnp[c], be = bnp[kC + c], m = bnp[2 * kC + c], va = bnp[3 * kC + c];
    float s = g / sqrtf(va + 1e-5f);
    float t = be - m * s;
    if (bias) t += bias[c] * s;
    scbase[which * 2 * kC + c] = s;
    scbase[which * 2 * kC + kC + c] = t;
}

__global__ void wprep_all_k(const float* __restrict__ rb_w1, const float* __restrict__ rb_w2,
                            const float* __restrict__ off_w, const float* __restrict__ dc_w,
                            const float* __restrict__ cv_w,
                            __half* __restrict__ w1, __half* __restrict__ w2,
                            __half* __restrict__ wo, __half* __restrict__ wd,
                            __half* __restrict__ wc) {
    int idx = blockIdx.x * 256 + threadIdx.x;
    if (idx < 147456) {
        int ci = idx & 127, oc = (idx >> 7) & 127, tap = idx >> 14;
        w1[idx] = __float2half_rn(rb_w1[(oc * kC + ci) * 9 + tap]);
    } else if (idx < 294912) {
        int i = idx - 147456;
        int ci = i & 127, oc = (i >> 7) & 127, tap = i >> 14;
        w2[i] = __float2half_rn(rb_w2[(oc * kC + ci) * 9 + tap]);
    } else if (idx < 368640) {
        int i = idx - 294912;
        int ci = i & 127, oc = (i >> 7) & 63, tap = i >> 13;
        wo[i] = __float2half_rn((oc < 54) ? off_w[(oc * kC + ci) * 9 + tap] : 0.f);
    } else if (idx < 516096) {
        int i = idx - 368640;
        int cg = i & 63, oc = (i >> 6) & 127, dk = i >> 13;
        int d = dk / 9, k = dk % 9;
        wd[i] = __float2half_rn(dc_w[(oc * kC + d * 64 + cg) * 9 + k]);
    } else if (idx < 532480) {
        int i = idx - 516096;
        wc[i] = __float2half_rn(cv_w[i]);
    }
}

__global__ void to_nhwc2_k(const float* __restrict__ in, float* __restrict__ outf,
                           __half* __restrict__ oh) {
    __shared__ float t[32][33];
    int b = blockIdx.z, c0 = blockIdx.y * 32, p0 = blockIdx.x * 32;
    int tx = threadIdx.x, ty = threadIdx.y;
#pragma unroll
    for (int k = 0; k < 32; k += 8)
        t[ty + k][tx] = in[(size_t)(b * kC + c0 + ty + k) * kHW + p0 + tx];
    __syncthreads();
#pragma unroll
    for (int k = 0; k < 32; k += 8) {
        float v = t[tx][ty + k];
        size_t o = (size_t)(b * kHW + p0 + ty + k) * kC + c0 + tx;
        outf[o] = v;
        oh[o] = __float2half_rn(v);
    }
}

// ======================= conv kernel (row-reuse implicit GEMM, fp16 1-pass) =======================
// CTA: one image row (128 px) x NT oc. Outer chunks: (ty) x (ci quarter).
// One haloed A-stage serves 3 tx taps via ldmatrix base shifts (+80 B = +1 px).
template <int NT, int EPI, int TAPS>
__global__ void __launch_bounds__(256, 2)
mma_conv_k(const __half* __restrict__ Ah, const __half* __restrict__ W,
           const float* __restrict__ scale, const float* __restrict__ shift,
           const float* __restrict__ resf, float* __restrict__ outf,
           __half* __restrict__ outh) {
    constexpr int MT   = NT / 64;
    constexpr int HALO = (TAPS == 9) ? 1 : 0;
    constexpr int NTX  = (TAPS == 9) ? 3 : 1;
    constexpr int NTY  = NTX;
    constexpr int PXS  = 128 + 2 * HALO;
    constexpr int PXSP = (TAPS == 9) ? 136 : 128;
    constexpr int ABUF = PXSP * 80;             // A bytes per buffer (single prec)
    constexpr int BPT  = NT * 80;               // B bytes per tap
    constexpr int BPB  = NTX * BPT;             // B bytes per buffer
    constexpr int NCH  = NTY * 4;               // staging chunks

    extern __shared__ char sm[];
    const uint32_t smA = smem_to_u32(sm);
    const uint32_t smB = smA + 2 * ABUF;

    const int h = blockIdx.x, b = blockIdx.y;
    const int tid = threadIdx.x, wid = tid >> 5, lane = tid & 31;
    const int wm = (NT == 128) ? (wid & 3) : wid;
    const int wn = (NT == 128) ? (wid >> 2) : 0;
    const int pxb = wm * MT * 16;
    const int ocb = wn * 64;

    float acc[MT * 8][4];
#pragma unroll
    for (int i = 0; i < MT * 8; i++)
#pragma unroll
        for (int j = 0; j < 4; j++) acc[i][j] = 0.f;

    auto stage = [&](int cc, int s) {
        const int ty = cc >> 2, cq = cc & 3, c0 = cq * 32;
        const int row = h + ty - HALO;
        const bool rok = (row >= 0) && (row < kH);
        // A: PXS slots x 32 ci
        constexpr int ATOT = PXS * 4;
#pragma unroll
        for (int it = 0; it < (ATOT + 255) / 256; it++) {
            int i = it * 256 + tid;
            if ((ATOT & 255) && i >= ATOT) break;
            int slot = i >> 2, j = i & 3;
            int inpx = slot - HALO;
            bool ok = rok && ((unsigned)inpx < 128u);
            const __half* src = Ah +
                ((size_t)(b * kHW + (ok ? row * kW + inpx : 0)) * kC + c0 + j * 8);
            cp16(smA + s * ABUF + slot * 80 + j * 16, src, ok);
        }
        // B: NTX taps x NT oc x 32 ci
#pragma unroll
        for (int it = 0; it < NTX * NT / 64; it++) {
            int i = it * 256 + tid;
            int txn = i / (NT * 4), rem = i % (NT * 4), oc = rem >> 2, j = rem & 3;
            int tap = ty * 3 + txn;
            const __half* src = W + ((size_t)(tap * NT + oc)) * kC + c0 + j * 8;
            cp16(smB + s * BPB + txn * BPT + oc * 80 + j * 16, src, true);
        }
    };

    stage(0, 0); cp_commit();
#pragma unroll 1
    for (int cc = 0; cc < NCH; cc++) {
        const int s = cc & 1;
        cp_wait0();
        __syncthreads();
        if (cc + 1 < NCH) { stage(cc + 1, s ^ 1); cp_commit(); }
#pragma unroll
        for (int tx = 0; tx < NTX; tx++) {
            mma_chunk<MT, 2>(smA + s * ABUF + tx * 80,
                             smB + s * BPB + tx * BPT,
                             80, 80, pxb, ocb, lane, acc);
        }
    }

    // ---- epilogue ----
    const int r4 = lane >> 2, cp2 = (lane & 3) * 2;
    const size_t rowbase = (size_t)(b * kHW + h * kW);
#pragma unroll
    for (int mt = 0; mt < MT; mt++)
#pragma unroll
        for (int nt = 0; nt < 8; nt++) {
            const int oc = ocb + nt * 8 + cp2;
            const float s0 = scale[oc], s1 = scale[oc + 1];
            const float sh0 = shift[oc], sh1 = shift[oc + 1];
#pragma unroll
            for (int hh = 0; hh < 2; hh++) {
                const int px = pxb + mt * 16 + r4 + hh * 8;
                float v0 = acc[mt * 8 + nt][hh * 2 + 0] * s0 + sh0;
                float v1 = acc[mt * 8 + nt][hh * 2 + 1] * s1 + sh1;
                const size_t pix = rowbase + px;
                if (EPI == 1) {
                    float2 rr = *(const float2*)(resf + pix * kC + oc);
                    v0 += rr.x; v1 += rr.y;
                }
                if (EPI == 0 || EPI == 1) { v0 = fmaxf(v0, 0.f); v1 = fmaxf(v1, 0.f); }
                if (EPI == 4) {
                    v0 = (v0 > 0.f) ? v0 : 0.1f * v0;
                    v1 = (v1 > 0.f) ? v1 : 0.1f * v1;
                    size_t i0 = (size_t)(b * kC + oc) * kHW + h * kW + px;
                    outf[i0] = resf[i0] + v0;
                    outf[i0 + kHW] = resf[i0 + kHW] + v1;
                } else if (EPI == 2) {
                    *(float2*)(outf + pix * 64 + oc) = make_float2(v0, v1);
                } else {
                    *(__half2*)(outh + pix * kC + oc) =
                        __halves2half2(__float2half_rn(v0), __float2half_rn(v1));
                    if (EPI == 1)
                        *(float2*)(outf + pix * kC + oc) = make_float2(v0, v1);
                }
            }
        }
}

// ======================= modulated deformable conv (1-pass fp16) =======================
__global__ void __launch_bounds__(256, 2)
mma_deform_k(const float* __restrict__ h2f, const float* __restrict__ offb,
             const __half* __restrict__ W,
             const float* __restrict__ scale, const float* __restrict__ shift,
             __half* __restrict__ outh) {
    constexpr int ABUF = 128 * 144;   // per A buffer (single prec)
    constexpr int BSZ  = 128 * 144;   // per B buffer

    extern __shared__ char sm[];
    const uint32_t smA = smem_to_u32(sm);
    const uint32_t smB = smA + 2 * ABUF;

    const int h = blockIdx.x, b = blockIdx.y;
    const int tid = threadIdx.x, wid = tid >> 5, lane = tid & 31;
    const int wm = wid & 3, wn = wid >> 2;
    const int pxb = wm * 32, ocb = wn * 64;
    const int spx = tid >> 1, half = tid & 1;

    float acc[16][4];
#pragma unroll
    for (int i = 0; i < 16; i++)
#pragma unroll
        for (int j = 0; j < 4; j++) acc[i][j] = 0.f;

    const float* op = offb + ((size_t)(b * kHW + h * kW + spx)) * 64;

    auto gath = [&](int dk, __half* hb) {
        int d = dk / 9, k = dk % 9;
        float oy = op[d * 18 + 2 * k], ox = op[d * 18 + 2 * k + 1];
        float ml = op[36 + d * 9 + k];
        float m = 1.f / (1.f + __expf(-ml));
        float py = oy + (float)(h + k / 3 - 1);
        float pxx = ox + (float)(spx + k % 3 - 1);
        float y0f = floorf(py), x0f = floorf(pxx);
        float fy = py - y0f, fx = pxx - x0f;
        int y0 = (int)y0f, x0 = (int)x0f;
        float cw[4] = {(1.f - fy) * (1.f - fx) * m, (1.f - fy) * fx * m,
                       fy * (1.f - fx) * m, fy * fx * m};
        int cy[4] = {y0, y0, y0 + 1, y0 + 1};
        int cx[4] = {x0, x0 + 1, x0, x0 + 1};
        float rr[32];
#pragma unroll
        for (int j = 0; j < 32; j++) rr[j] = 0.f;
        const float* bp = h2f + (size_t)b * kHW * kC + d * 64 + half * 32;
#pragma unroll
        for (int cn = 0; cn < 4; cn++) {
            int y = cy[cn], x = cx[cn];
            if (y >= 0 && y < kH && x >= 0 && x < kW) {
                const float4* p4 = (const float4*)(bp + (size_t)(y * kW + x) * kC);
                float wg = cw[cn];
#pragma unroll
                for (int q = 0; q < 8; q++) {
                    float4 u4 = p4[q];
                    rr[q * 4 + 0] += wg * u4.x; rr[q * 4 + 1] += wg * u4.y;
                    rr[q * 4 + 2] += wg * u4.z; rr[q * 4 + 3] += wg * u4.w;
                }
            }
        }
#pragma unroll
        for (int j = 0; j < 32; j++) hb[j] = __float2half_rn(rr[j]);
    };

    auto sts = [&](int s, const __half* hb) {
        uint32_t bofs = spx * 144 + half * 64;
#pragma unroll
        for (int q = 0; q < 4; q++)
            *(uint4*)(sm + (size_t)s * ABUF + bofs + q * 16) = ((const uint4*)hb)[q];
    };

    auto stageB = [&](int dk, int s) {
#pragma unroll
        for (int it = 0; it < 4; it++) {
            int i = it * 256 + tid;
            int oc = i >> 3, j = i & 7;
            const __half* src = W + ((size_t)(dk * 128 + oc)) * 64 + j * 8;
            cp16(smB + s * BSZ + oc * 144 + j * 16, src, true);
        }
    };

    __align__(16) __half hb[32];
    gath(0, hb);
    sts(0, hb);
    stageB(0, 0); cp_commit();

#pragma unroll 1
    for (int dk = 0; dk < 18; dk++) {
        const int s = dk & 1;
        const bool more = (dk + 1 < 18);
        if (more) {
            gath(dk + 1, hb);                // overlaps other warps' mma(dk-1)
            stageB(dk + 1, s ^ 1); cp_commit();
            cp_wait1();                      // B(dk) landed
        } else {
            cp_wait0();
        }
        __syncthreads();                     // mma(dk-1) done everywhere; STS(dk) visible
        if (more) sts(s ^ 1, hb);            // overlaps mma(dk) of other warps
        mma_chunk<2, 4>(smA + s * ABUF, smB + s * BSZ,
                        144, 144, pxb, ocb, lane, acc);
    }

    // ---- epilogue: leaky(bn) -> fp16 NHWC ----
    const int r4 = lane >> 2, cp2 = (lane & 3) * 2;
    const size_t rowbase = (size_t)(b * kHW + h * kW);
#pragma unroll
    for (int mt = 0; mt < 2; mt++)
#pragma unroll
        for (int nt = 0; nt < 8; nt++) {
            const int oc = ocb + nt * 8 + cp2;
            const float s0 = scale[oc], s1 = scale[oc + 1];
            const float sh0 = shift[oc], sh1 = shift[oc + 1];
#pragma unroll
            for (int hh = 0; hh < 2; hh++) {
                const int px = pxb + mt * 16 + r4 + hh * 8;
                float v0 = acc[mt * 8 + nt][hh * 2 + 0] * s0 + sh0;
                float v1 = acc[mt * 8 + nt][hh * 2 + 1] * s1 + sh1;
                v0 = (v0 > 0.f) ? v0 : 0.1f * v0;
                v1 = (v1 > 0.f) ? v1 : 0.1f * v1;
                const size_t pix = rowbase + px;
                *(__half2*)(outh + pix * kC + oc) =
                    __halves2half2(__float2half_rn(v0), __float2half_rn(v1));
            }
        }
}

// ======================= launch =======================
extern "C" void kernel_launch(void* const* d_in, const int* in_sizes, int n_in,
                              void* d_out, int out_size) {
    (void)in_sizes; (void)n_in; (void)out_size;
    const float* x      = (const float*)d_in[0];
    const float* rb_w1  = (const float*)d_in[1];
    const float* rb_b1  = (const float*)d_in[2];
    const float* rb_bn1 = (const float*)d_in[3];
    const float* rb_w2  = (const float*)d_in[4];
    const float* rb_b2  = (const float*)d_in[5];
    const float* rb_bn2 = (const float*)d_in[6];
    const float* off_w  = (const float*)d_in[7];
    const float* off_b  = (const float*)d_in[8];
    const float* dc_w   = (const float*)d_in[9];
    const float* dc_b   = (const float*)d_in[10];
    const float* bn1    = (const float*)d_in[11];
    const float* cv2_w  = (const float*)d_in[12];
    const float* bn2    = (const float*)d_in[13];
    float* out = (float*)d_out;

    float* base = nullptr;
    cudaGetSymbolAddress((void**)&base, g_buf);
    float* xt    = base + O_XT;
    float* h2f   = base + O_H2F;
    float* offb_ = base + O_OFFB;
    __half* xh  = (__half*)(base + O_XH);
    __half* h1h = (__half*)(base + O_H1H);
    __half* h2h = (__half*)(base + O_H2H);
    __half* h3h = (__half*)(base + O_H3H);
    __half* w1 = (__half*)(base + O_W1);
    __half* w2 = (__half*)(base + O_W2);
    __half* wd = (__half*)(base + O_WD);
    __half* wo = (__half*)(base + O_WO);
    __half* wc = (__half*)(base + O_WC);
    float* scb = base + O_SC;
    float* s1 = scb + 0 * kC;   float* t1 = scb + 1 * kC;
    float* s2 = scb + 2 * kC;   float* t2 = scb + 3 * kC;
    float* s3 = scb + 4 * kC;   float* t3 = scb + 5 * kC;
    float* s4 = scb + 6 * kC;   float* t4 = scb + 7 * kC;
    float* soff = scb + 8 * kC; float* toff = soff + 64;

    wprep_all_k<<<(532480 + 255) / 256, 256>>>(rb_w1, rb_w2, off_w, dc_w, cv2_w,
                                               w1, w2, wo, wd, wc);
    prep_bn_all_k<<<5, kC>>>(rb_bn1, rb_b1, rb_bn2, rb_b2, bn1, dc_b, bn2, off_b, scb);
    to_nhwc2_k<<<dim3(kHW / 32, kC / 32, kB), dim3(32, 8)>>>(x, xt, xh);

    constexpr int SM1  = 2 * (136 * 80) + 2 * (3 * 128 * 80);  // 83200
    constexpr int SMO  = 2 * (136 * 80) + 2 * (3 * 64 * 80);   // 52480
    constexpr int SMC  = 2 * (128 * 80) + 2 * (1 * 128 * 80);  // 40960
    constexpr int SMDEF = 2 * (128 * 144) + 2 * (128 * 144);   // 73728
    dim3 grid(kH, kB);

    cudaFuncSetAttribute(mma_conv_k<128, 0, 9>, cudaFuncAttributeMaxDynamicSharedMemorySize, SM1);
    cudaFuncSetAttribute(mma_conv_k<128, 1, 9>, cudaFuncAttributeMaxDynamicSharedMemorySize, SM1);
    cudaFuncSetAttribute(mma_conv_k<64, 2, 9>,  cudaFuncAttributeMaxDynamicSharedMemorySize, SMO);
    cudaFuncSetAttribute(mma_conv_k<128, 4, 1>, cudaFuncAttributeMaxDynamicSharedMemorySize, SMC);
    cudaFuncSetAttribute(mma_deform_k,          cudaFuncAttributeMaxDynamicSharedMemorySize, SMDEF);

    mma_conv_k<128, 0, 9><<<grid, 256, SM1>>>(xh, w1, s1, t1,
                                              nullptr, nullptr, h1h);
    mma_conv_k<128, 1, 9><<<grid, 256, SM1>>>(h1h, w2, s2, t2,
                                              xt, h2f, h2h);
    mma_conv_k<64, 2, 9><<<grid, 256, SMO>>>(h2h, wo, soff, toff,
                                             nullptr, offb_, nullptr);
    mma_deform_k<<<grid, 256, SMDEF>>>(h2f, offb_, wd, s3, t3, h3h);
    mma_conv_k<128, 4, 1><<<grid, 256, SMC>>>(h3h, wc, s4, t4,
                                              x, out, nullptr);
}

// round 13
// speedup vs baseline: 2.7457x; 1.5377x over previous
#include <cuda_runtime.h>
#include <cuda_fp16.h>
#include <cstdint>
#include <cstddef>

#define DEV_INLINE __device__ __forceinline__

constexpr int kB = 4, kC = 128, kH = 128, kW = 128;
constexpr int kHW = kH * kW;

// ======================= scratch (floats) =======================
constexpr size_t O_XT   = 0;
constexpr size_t O_OFFB = 16777216;
constexpr size_t O_XH   = 20971520;   // fp16 activations (each 8.4M halves)
constexpr size_t O_H1H  = 25165824;
constexpr size_t O_H2H  = 29360128;
constexpr size_t O_H3H  = 33554432;
constexpr size_t O_W1   = 54525952;
constexpr size_t O_W2   = 54599680;
constexpr size_t O_WD   = 54673408;
constexpr size_t O_WO   = 54747136;
constexpr size_t O_WC   = 54820864;
constexpr size_t O_SC   = 55058432;
constexpr size_t SCRATCH= 55060608;

__device__ float g_buf[SCRATCH];

// ======================= PTX helpers =======================
DEV_INLINE uint32_t smem_to_u32(const void* p) {
    uint32_t a;
    asm("{ .reg .u64 t; cvta.to.shared.u64 t, %1; cvt.u32.u64 %0, t; }" : "=r"(a) : "l"(p));
    return a;
}
DEV_INLINE void cp16(uint32_t d, const void* s, bool ok) {
    asm volatile("cp.async.ca.shared.global [%0], [%1], 16, %2;"
                 :: "r"(d), "l"(s), "r"(ok ? 16 : 0));
}
DEV_INLINE void cp_commit() { asm volatile("cp.async.commit_group;" ::: "memory"); }
DEV_INLINE void cp_wait0()  { asm volatile("cp.async.wait_group 0;" ::: "memory"); }
DEV_INLINE void cp_wait1()  { asm volatile("cp.async.wait_group 1;" ::: "memory"); }

DEV_INLINE void ldsm4(uint32_t a, uint32_t& r0, uint32_t& r1, uint32_t& r2, uint32_t& r3) {
    asm volatile("ldmatrix.sync.aligned.m8n8.x4.shared.b16 {%0,%1,%2,%3}, [%4];"
                 : "=r"(r0), "=r"(r1), "=r"(r2), "=r"(r3) : "r"(a));
}
DEV_INLINE void mma16816(float* c, const uint32_t* a, const uint32_t* b) {
    asm volatile("mma.sync.aligned.m16n8k16.row.col.f32.f16.f16.f32 "
                 "{%0,%1,%2,%3},{%4,%5,%6,%7},{%8,%9},{%0,%1,%2,%3};"
                 : "+f"(c[0]), "+f"(c[1]), "+f"(c[2]), "+f"(c[3])
                 : "r"(a[0]), "r"(a[1]), "r"(a[2]), "r"(a[3]), "r"(b[0]), "r"(b[1]));
}

// single-pass mma over one staged K-chunk: MT m-tiles x 8 n-tiles, KS k16 steps.
template <int MT, int KS>
DEV_INLINE void mma_chunk(uint32_t A, uint32_t B,
                          int as, int bs, int pxb, int ocb, int lane, float (*acc)[4]) {
    const int r = lane & 7, sel = lane >> 3;
    const int aro = (pxb + (sel & 1) * 8 + r) * as;
    const int bro = (ocb + (sel >> 1) * 8 + r) * bs;
#pragma unroll
    for (int ks = 0; ks < KS; ks++) {
        const int ac = (ks * 16 + (sel >> 1) * 8) * 2;
        const int bc = (ks * 16 + (sel & 1) * 8) * 2;
        uint32_t ah[MT][4];
#pragma unroll
        for (int mt = 0; mt < MT; mt++)
            ldsm4(A + aro + mt * 16 * as + ac, ah[mt][0], ah[mt][1], ah[mt][2], ah[mt][3]);
        uint32_t bh[8][2];
#pragma unroll
        for (int jp = 0; jp < 4; jp++) {
            ldsm4(B + bro + jp * 16 * bs + bc,
                  bh[2 * jp][0], bh[2 * jp][1], bh[2 * jp + 1][0], bh[2 * jp + 1][1]);
        }
#pragma unroll
        for (int mt = 0; mt < MT; mt++)
#pragma unroll
            for (int nt = 0; nt < 8; nt++)
                mma16816(acc[mt * 8 + nt], ah[mt], bh[nt]);
    }
}

// ======================= prep kernels =======================
__global__ void prep_bn_all_k(const float* __restrict__ rb_bn1, const float* __restrict__ rb_b1,
                              const float* __restrict__ rb_bn2, const float* __restrict__ rb_b2,
                              const float* __restrict__ bn1, const float* __restrict__ dc_b,
                              const float* __restrict__ bn2, const float* __restrict__ off_b,
                              float* __restrict__ scbase) {
    int which = blockIdx.x, c = threadIdx.x;
    if (which == 4) {
        if (c < 64) {
            scbase[8 * kC + c] = 1.f;
            scbase[8 * kC + 64 + c] = (c < 54) ? off_b[c] : 0.f;
        }
        return;
    }
    const float* bnp = (which == 0) ? rb_bn1 : (which == 1) ? rb_bn2 : (which == 2) ? bn1 : bn2;
    const float* bias = (which == 0) ? rb_b1 : (which == 1) ? rb_b2 : (which == 2) ? dc_b : nullptr;
    float g = bnp[c], be = bnp[kC + c], m = bnp[2 * kC + c], va = bnp[3 * kC + c];
    float s = g / sqrtf(va + 1e-5f);
    float t = be - m * s;
    if (bias) t += bias[c] * s;
    scbase[which * 2 * kC + c] = s;
    scbase[which * 2 * kC + kC + c] = t;
}

__global__ void wprep_all_k(const float* __restrict__ rb_w1, const float* __restrict__ rb_w2,
                            const float* __restrict__ off_w, const float* __restrict__ dc_w,
                            const float* __restrict__ cv_w,
                            __half* __restrict__ w1, __half* __restrict__ w2,
                            __half* __restrict__ wo, __half* __restrict__ wd,
                            __half* __restrict__ wc) {
    int idx = blockIdx.x * 256 + threadIdx.x;
    if (idx < 147456) {
        int ci = idx & 127, oc = (idx >> 7) & 127, tap = idx >> 14;
        w1[idx] = __float2half_rn(rb_w1[(oc * kC + ci) * 9 + tap]);
    } else if (idx < 294912) {
        int i = idx - 147456;
        int ci = i & 127, oc = (i >> 7) & 127, tap = i >> 14;
        w2[i] = __float2half_rn(rb_w2[(oc * kC + ci) * 9 + tap]);
    } else if (idx < 368640) {
        int i = idx - 294912;
        int ci = i & 127, oc = (i >> 7) & 63, tap = i >> 13;
        wo[i] = __float2half_rn((oc < 54) ? off_w[(oc * kC + ci) * 9 + tap] : 0.f);
    } else if (idx < 516096) {
        int i = idx - 368640;
        int cg = i & 63, oc = (i >> 6) & 127, dk = i >> 13;
        int d = dk / 9, k = dk % 9;
        wd[i] = __float2half_rn(dc_w[(oc * kC + d * 64 + cg) * 9 + k]);
    } else if (idx < 532480) {
        int i = idx - 516096;
        wc[i] = __float2half_rn(cv_w[i]);
    }
}

__global__ void to_nhwc2_k(const float* __restrict__ in, float* __restrict__ outf,
                           __half* __restrict__ oh) {
    __shared__ float t[32][33];
    int b = blockIdx.z, c0 = blockIdx.y * 32, p0 = blockIdx.x * 32;
    int tx = threadIdx.x, ty = threadIdx.y;
#pragma unroll
    for (int k = 0; k < 32; k += 8)
        t[ty + k][tx] = in[(size_t)(b * kC + c0 + ty + k) * kHW + p0 + tx];
    __syncthreads();
#pragma unroll
    for (int k = 0; k < 32; k += 8) {
        float v = t[tx][ty + k];
        size_t o = (size_t)(b * kHW + p0 + ty + k) * kC + c0 + tx;
        outf[o] = v;
        oh[o] = __float2half_rn(v);
    }
}

// ======================= conv kernel (row-reuse implicit GEMM, fp16 1-pass) =======================
// EPI: 0 relu -> fp16   1 relu(+fp32 res) -> fp16   2 raw -> fp32 (stride 64)
//      4 leaky + x(NCHW) -> NCHW fp32
template <int NT, int EPI, int TAPS>
__global__ void __launch_bounds__(256, 2)
mma_conv_k(const __half* __restrict__ Ah, const __half* __restrict__ W,
           const float* __restrict__ scale, const float* __restrict__ shift,
           const float* __restrict__ resf, float* __restrict__ outf,
           __half* __restrict__ outh) {
    constexpr int MT   = NT / 64;
    constexpr int HALO = (TAPS == 9) ? 1 : 0;
    constexpr int NTX  = (TAPS == 9) ? 3 : 1;
    constexpr int NTY  = NTX;
    constexpr int PXS  = 128 + 2 * HALO;
    constexpr int PXSP = (TAPS == 9) ? 136 : 128;
    constexpr int ABUF = PXSP * 80;
    constexpr int BPT  = NT * 80;
    constexpr int BPB  = NTX * BPT;
    constexpr int NCH  = NTY * 4;

    extern __shared__ char sm[];
    const uint32_t smA = smem_to_u32(sm);
    const uint32_t smB = smA + 2 * ABUF;

    const int h = blockIdx.x, b = blockIdx.y;
    const int tid = threadIdx.x, wid = tid >> 5, lane = tid & 31;
    const int wm = (NT == 128) ? (wid & 3) : wid;
    const int wn = (NT == 128) ? (wid >> 2) : 0;
    const int pxb = wm * MT * 16;
    const int ocb = wn * 64;

    float acc[MT * 8][4];
#pragma unroll
    for (int i = 0; i < MT * 8; i++)
#pragma unroll
        for (int j = 0; j < 4; j++) acc[i][j] = 0.f;

    auto stage = [&](int cc, int s) {
        const int ty = cc >> 2, cq = cc & 3, c0 = cq * 32;
        const int row = h + ty - HALO;
        const bool rok = (row >= 0) && (row < kH);
        constexpr int ATOT = PXS * 4;
#pragma unroll
        for (int it = 0; it < (ATOT + 255) / 256; it++) {
            int i = it * 256 + tid;
            if ((ATOT & 255) && i >= ATOT) break;
            int slot = i >> 2, j = i & 3;
            int inpx = slot - HALO;
            bool ok = rok && ((unsigned)inpx < 128u);
            const __half* src = Ah +
                ((size_t)(b * kHW + (ok ? row * kW + inpx : 0)) * kC + c0 + j * 8);
            cp16(smA + s * ABUF + slot * 80 + j * 16, src, ok);
        }
#pragma unroll
        for (int it = 0; it < NTX * NT / 64; it++) {
            int i = it * 256 + tid;
            int txn = i / (NT * 4), rem = i % (NT * 4), oc = rem >> 2, j = rem & 3;
            int tap = ty * 3 + txn;
            const __half* src = W + ((size_t)(tap * NT + oc)) * kC + c0 + j * 8;
            cp16(smB + s * BPB + txn * BPT + oc * 80 + j * 16, src, true);
        }
    };

    stage(0, 0); cp_commit();
#pragma unroll 1
    for (int cc = 0; cc < NCH; cc++) {
        const int s = cc & 1;
        cp_wait0();
        __syncthreads();
        if (cc + 1 < NCH) { stage(cc + 1, s ^ 1); cp_commit(); }
#pragma unroll
        for (int tx = 0; tx < NTX; tx++) {
            mma_chunk<MT, 2>(smA + s * ABUF + tx * 80,
                             smB + s * BPB + tx * BPT,
                             80, 80, pxb, ocb, lane, acc);
        }
    }

    // ---- epilogue ----
    const int r4 = lane >> 2, cp2 = (lane & 3) * 2;
    const size_t rowbase = (size_t)(b * kHW + h * kW);
#pragma unroll
    for (int mt = 0; mt < MT; mt++)
#pragma unroll
        for (int nt = 0; nt < 8; nt++) {
            const int oc = ocb + nt * 8 + cp2;
            const float s0 = scale[oc], s1 = scale[oc + 1];
            const float sh0 = shift[oc], sh1 = shift[oc + 1];
#pragma unroll
            for (int hh = 0; hh < 2; hh++) {
                const int px = pxb + mt * 16 + r4 + hh * 8;
                float v0 = acc[mt * 8 + nt][hh * 2 + 0] * s0 + sh0;
                float v1 = acc[mt * 8 + nt][hh * 2 + 1] * s1 + sh1;
                const size_t pix = rowbase + px;
                if (EPI == 1) {
                    float2 rr = *(const float2*)(resf + pix * kC + oc);
                    v0 += rr.x; v1 += rr.y;
                }
                if (EPI == 0 || EPI == 1) { v0 = fmaxf(v0, 0.f); v1 = fmaxf(v1, 0.f); }
                if (EPI == 4) {
                    v0 = (v0 > 0.f) ? v0 : 0.1f * v0;
                    v1 = (v1 > 0.f) ? v1 : 0.1f * v1;
                    size_t i0 = (size_t)(b * kC + oc) * kHW + h * kW + px;
                    outf[i0] = resf[i0] + v0;
                    outf[i0 + kHW] = resf[i0 + kHW] + v1;
                } else if (EPI == 2) {
                    *(float2*)(outf + pix * 64 + oc) = make_float2(v0, v1);
                } else {
                    *(__half2*)(outh + pix * kC + oc) =
                        __halves2half2(__float2half_rn(v0), __float2half_rn(v1));
                }
            }
        }
}

// ======================= modulated deformable conv (fp16 gather, 1-pass) =======================
__global__ void __launch_bounds__(256, 2)
mma_deform_k(const __half* __restrict__ h2h, const float* __restrict__ offb,
             const __half* __restrict__ W,
             const float* __restrict__ scale, const float* __restrict__ shift,
             __half* __restrict__ outh) {
    constexpr int ABUF = 128 * 144;
    constexpr int BSZ  = 128 * 144;

    extern __shared__ char sm[];
    const uint32_t smA = smem_to_u32(sm);
    const uint32_t smB = smA + 2 * ABUF;

    const int h = blockIdx.x, b = blockIdx.y;
    const int tid = threadIdx.x, wid = tid >> 5, lane = tid & 31;
    const int wm = wid & 3, wn = wid >> 2;
    const int pxb = wm * 32, ocb = wn * 64;
    const int spx = tid >> 1, half = tid & 1;

    float acc[16][4];
#pragma unroll
    for (int i = 0; i < 16; i++)
#pragma unroll
        for (int j = 0; j < 4; j++) acc[i][j] = 0.f;

    const float* op = offb + ((size_t)(b * kHW + h * kW + spx)) * 64;

    auto gath = [&](int dk, __half* hb) {
        int d = dk / 9, k = dk % 9;
        float oy = op[d * 18 + 2 * k], ox = op[d * 18 + 2 * k + 1];
        float ml = op[36 + d * 9 + k];
        float m = 1.f / (1.f + __expf(-ml));
        float py = oy + (float)(h + k / 3 - 1);
        float pxx = ox + (float)(spx + k % 3 - 1);
        float y0f = floorf(py), x0f = floorf(pxx);
        float fy = py - y0f, fx = pxx - x0f;
        int y0 = (int)y0f, x0 = (int)x0f;
        float cw[4] = {(1.f - fy) * (1.f - fx) * m, (1.f - fy) * fx * m,
                       fy * (1.f - fx) * m, fy * fx * m};
        int cy[4] = {y0, y0, y0 + 1, y0 + 1};
        int cx[4] = {x0, x0 + 1, x0, x0 + 1};
        float rr[32];
#pragma unroll
        for (int j = 0; j < 32; j++) rr[j] = 0.f;
        const __half* bp = h2h + (size_t)b * kHW * kC + d * 64 + half * 32;
#pragma unroll
        for (int cn = 0; cn < 4; cn++) {
            int y = cy[cn], x = cx[cn];
            if (y >= 0 && y < kH && x >= 0 && x < kW) {
                const uint4* p4 = (const uint4*)(bp + (size_t)(y * kW + x) * kC);
                float wg = cw[cn];
#pragma unroll
                for (int q = 0; q < 4; q++) {
                    uint4 u = p4[q];
                    const __half2* hp = (const __half2*)&u;
#pragma unroll
                    for (int t = 0; t < 4; t++) {
                        float2 f = __half22float2(hp[t]);
                        rr[q * 8 + t * 2 + 0] += wg * f.x;
                        rr[q * 8 + t * 2 + 1] += wg * f.y;
                    }
                }
            }
        }
#pragma unroll
        for (int j = 0; j < 32; j++) hb[j] = __float2half_rn(rr[j]);
    };

    auto sts = [&](int s, const __half* hb) {
        uint32_t bofs = spx * 144 + half * 64;
#pragma unroll
        for (int q = 0; q < 4; q++)
            *(uint4*)(sm + (size_t)s * ABUF + bofs + q * 16) = ((const uint4*)hb)[q];
    };

    auto stageB = [&](int dk, int s) {
#pragma unroll
        for (int it = 0; it < 4; it++) {
            int i = it * 256 + tid;
            int oc = i >> 3, j = i & 7;
            const __half* src = W + ((size_t)(dk * 128 + oc)) * 64 + j * 8;
            cp16(smB + s * BSZ + oc * 144 + j * 16, src, true);
        }
    };

    __align__(16) __half hb[32];
    gath(0, hb);
    sts(0, hb);
    stageB(0, 0); cp_commit();

#pragma unroll 1
    for (int dk = 0; dk < 18; dk++) {
        const int s = dk & 1;
        const bool more = (dk + 1 < 18);
        if (more) {
            gath(dk + 1, hb);                // overlaps other warps' mma(dk-1)
            stageB(dk + 1, s ^ 1); cp_commit();
            cp_wait1();                      // B(dk) landed
        } else {
            cp_wait0();
        }
        __syncthreads();                     // mma(dk-1) done everywhere; STS(dk) visible
        if (more) sts(s ^ 1, hb);            // overlaps mma(dk) of other warps
        mma_chunk<2, 4>(smA + s * ABUF, smB + s * BSZ,
                        144, 144, pxb, ocb, lane, acc);
    }

    // ---- epilogue: leaky(bn) -> fp16 NHWC ----
    const int r4 = lane >> 2, cp2 = (lane & 3) * 2;
    const size_t rowbase = (size_t)(b * kHW + h * kW);
#pragma unroll
    for (int mt = 0; mt < 2; mt++)
#pragma unroll
        for (int nt = 0; nt < 8; nt++) {
            const int oc = ocb + nt * 8 + cp2;
            const float s0 = scale[oc], s1 = scale[oc + 1];
            const float sh0 = shift[oc], sh1 = shift[oc + 1];
#pragma unroll
            for (int hh = 0; hh < 2; hh++) {
                const int px = pxb + mt * 16 + r4 + hh * 8;
                float v0 = acc[mt * 8 + nt][hh * 2 + 0] * s0 + sh0;
                float v1 = acc[mt * 8 + nt][hh * 2 + 1] * s1 + sh1;
                v0 = (v0 > 0.f) ? v0 : 0.1f * v0;
                v1 = (v1 > 0.f) ? v1 : 0.1f * v1;
                const size_t pix = rowbase + px;
                *(__half2*)(outh + pix * kC + oc) =
                    __halves2half2(__float2half_rn(v0), __float2half_rn(v1));
            }
        }
}

// ======================= launch =======================
extern "C" void kernel_launch(void* const* d_in, const int* in_sizes, int n_in,
                              void* d_out, int out_size) {
    (void)in_sizes; (void)n_in; (void)out_size;
    const float* x      = (const float*)d_in[0];
    const float* rb_w1  = (const float*)d_in[1];
    const float* rb_b1  = (const float*)d_in[2];
    const float* rb_bn1 = (const float*)d_in[3];
    const float* rb_w2  = (const float*)d_in[4];
    const float* rb_b2  = (const float*)d_in[5];
    const float* rb_bn2 = (const float*)d_in[6];
    const float* off_w  = (const float*)d_in[7];
    const float* off_b  = (const float*)d_in[8];
    const float* dc_w   = (const float*)d_in[9];
    const float* dc_b   = (const float*)d_in[10];
    const float* bn1    = (const float*)d_in[11];
    const float* cv2_w  = (const float*)d_in[12];
    const float* bn2    = (const float*)d_in[13];
    float* out = (float*)d_out;

    float* base = nullptr;
    cudaGetSymbolAddress((void**)&base, g_buf);
    float* xt    = base + O_XT;
    float* offb_ = base + O_OFFB;
    __half* xh  = (__half*)(base + O_XH);
    __half* h1h = (__half*)(base + O_H1H);
    __half* h2h = (__half*)(base + O_H2H);
    __half* h3h = (__half*)(base + O_H3H);
    __half* w1 = (__half*)(base + O_W1);
    __half* w2 = (__half*)(base + O_W2);
    __half* wd = (__half*)(base + O_WD);
    __half* wo = (__half*)(base + O_WO);
    __half* wc = (__half*)(base + O_WC);
    float* scb = base + O_SC;
    float* s1 = scb + 0 * kC;   float* t1 = scb + 1 * kC;
    float* s2 = scb + 2 * kC;   float* t2 = scb + 3 * kC;
    float* s3 = scb + 4 * kC;   float* t3 = scb + 5 * kC;
    float* s4 = scb + 6 * kC;   float* t4 = scb + 7 * kC;
    float* soff = scb + 8 * kC; float* toff = soff + 64;

    wprep_all_k<<<(532480 + 255) / 256, 256>>>(rb_w1, rb_w2, off_w, dc_w, cv2_w,
                                               w1, w2, wo, wd, wc);
    prep_bn_all_k<<<5, kC>>>(rb_bn1, rb_b1, rb_bn2, rb_b2, bn1, dc_b, bn2, off_b, scb);
    to_nhwc2_k<<<dim3(kHW / 32, kC / 32, kB), dim3(32, 8)>>>(x, xt, xh);

    constexpr int SM1  = 2 * (136 * 80) + 2 * (3 * 128 * 80);  // 83200
    constexpr int SMO  = 2 * (136 * 80) + 2 * (3 * 64 * 80);   // 52480
    constexpr int SMC  = 2 * (128 * 80) + 2 * (1 * 128 * 80);  // 40960
    constexpr int SMDEF = 2 * (128 * 144) + 2 * (128 * 144);   // 73728
    dim3 grid(kH, kB);

    cudaFuncSetAttribute(mma_conv_k<128, 0, 9>, cudaFuncAttributeMaxDynamicSharedMemorySize, SM1);
    cudaFuncSetAttribute(mma_conv_k<128, 1, 9>, cudaFuncAttributeMaxDynamicSharedMemorySize, SM1);
    cudaFuncSetAttribute(mma_conv_k<64, 2, 9>,  cudaFuncAttributeMaxDynamicSharedMemorySize, SMO);
    cudaFuncSetAttribute(mma_conv_k<128, 4, 1>, cudaFuncAttributeMaxDynamicSharedMemorySize, SMC);
    cudaFuncSetAttribute(mma_deform_k,          cudaFuncAttributeMaxDynamicSharedMemorySize, SMDEF);

    mma_conv_k<128, 0, 9><<<grid, 256, SM1>>>(xh, w1, s1, t1,
                                              nullptr, nullptr, h1h);
    mma_conv_k<128, 1, 9><<<grid, 256, SM1>>>(h1h, w2, s2, t2,
                                              xt, nullptr, h2h);
    mma_conv_k<64, 2, 9><<<grid, 256, SMO>>>(h2h, wo, soff, toff,
                                             nullptr, offb_, nullptr);
    mma_deform_k<<<grid, 256, SMDEF>>>(h2h, offb_, wd, s3, t3, h3h);
    mma_conv_k<128, 4, 1><<<grid, 256, SMC>>>(h3h, wc, s4, t4,
                                              x, out, nullptr);
}